// round 1
// baseline (speedup 1.0000x reference)
#include <cuda_runtime.h>
#include <math.h>

#define BATCH 4
#define C 192
#define HW 16384            // 128*128
#define NPIX (BATCH*HW)     // 65536
#define NH 6
#define HD 32
#define NWIN 256            // total windows (4 * 8 * 8)
#define NTOK 256            // tokens per window (16*16)

// ---------------- scratch (device globals; no allocations allowed) ----------
__device__ float g_y[BATCH*C*HW];           // 50 MB
__device__ float g_a[BATCH*C*HW];           // 50 MB
__device__ float g_b[BATCH*C*HW];           // 50 MB
__device__ float g_qkv[(size_t)NPIX*576];   // 151 MB
__device__ float g_tbl[961*NH];             // CPB bias table (16*sigmoid applied)

// ---------------- fast exp on the FMA pipe (avoids MUFU bottleneck) ---------
__device__ __forceinline__ float fexp(float x){
    // exp(x) = 2^(x*log2e); valid for x <= 0 path used here (softmax)
    float z  = fmaxf(x * 1.44269504088896f, -126.0f);
    float mz = z + 12582912.0f;                 // 1.5 * 2^23 round-to-nearest magic
    int   iz = __float_as_int(mz);              // low bits hold round(z)
    float zi = mz - 12582912.0f;
    float f  = z - zi;                          // f in [-0.5, 0.5]
    float p  = 1.0f + f*(0.6931471806f + f*(0.2402265070f + f*(0.0555041087f
              + f*(0.0096181291f + f*0.0013333558f))));
    return __int_as_float(__float_as_int(p) + (iz << 23));
}

// ---------------- CPB MLP: build 961x6 table of 16*sigmoid(bias) ------------
__global__ void k_cpb(const float* __restrict__ w1, const float* __restrict__ b1,
                      const float* __restrict__ w2, float* __restrict__ tbl)
{
    int r = blockIdx.x;          // 0..960
    int t = threadIdx.x;         // 128 threads
    float dy = (float)(r / 31) - 15.0f;
    float dx = (float)(r % 31) - 15.0f;
    float u0 = dy / 15.0f * 8.0f, u1 = dx / 15.0f * 8.0f;
    float t0 = copysignf(log2f(fabsf(u0) + 1.0f) * (1.0f/3.0f), u0);
    float t1 = copysignf(log2f(fabsf(u1) + 1.0f) * (1.0f/3.0f), u1);
    float acc[6] = {0,0,0,0,0,0};
    for (int u = t; u < 512; u += 128){
        float hv = fmaxf(w1[2*u]*t0 + w1[2*u+1]*t1 + b1[u], 0.0f);
        #pragma unroll
        for (int h = 0; h < 6; h++) acc[h] += hv * w2[h*512 + u];
    }
    __shared__ float red[6][128];
    #pragma unroll
    for (int h = 0; h < 6; h++) red[h][t] = acc[h];
    __syncthreads();
    for (int off = 64; off > 0; off >>= 1){
        if (t < off){
            #pragma unroll
            for (int h = 0; h < 6; h++) red[h][t] += red[h][t+off];
        }
        __syncthreads();
    }
    if (t < 6){
        float v = red[t][0];
        tbl[r*6 + t] = 16.0f / (1.0f + expf(-v));
    }
}

// ---------------- 1x1 conv (NCHW): out[co][p] = sum_k W[co][k] X[k][p] ------
// MODE 0: +bias, GELU, write NCHW      (p1)
// MODE 1: +bias, write NCHW            (pw)
// MODE 2: X := X .* X2, +bias +res(x), write BHWC (p2 + residual)
template<int MODE>
__global__ void k_conv1x1(const float* __restrict__ X, const float* __restrict__ Wg,
                          const float* __restrict__ bias, const float* __restrict__ X2,
                          const float* __restrict__ res, float* __restrict__ out)
{
    __shared__ float Ws[16][64];
    __shared__ float Xs[16][64];
    __shared__ float stage[64][65];

    const int tx = threadIdx.x, ty = threadIdx.y;
    const int tid = ty*16 + tx;
    const int p0  = blockIdx.x * 64;
    const int co0 = blockIdx.y * 64;
    const int b   = blockIdx.z;
    const float* Xb  = X + (size_t)b*C*HW;
    const float* X2b = (MODE==2) ? (X2 + (size_t)b*C*HW) : nullptr;

    float acc[4][4] = {};
    const int lr = tid >> 2;          // 0..63
    const int lk = (tid & 3) * 4;     // 0,4,8,12
    const int kk = tid >> 4;          // 0..15
    const int pq = (tid & 15) * 4;    // 0..60

    for (int k0 = 0; k0 < 192; k0 += 16){
        float4 wv = *(const float4*)&Wg[(size_t)(co0+lr)*192 + k0 + lk];
        Ws[lk+0][lr]=wv.x; Ws[lk+1][lr]=wv.y; Ws[lk+2][lr]=wv.z; Ws[lk+3][lr]=wv.w;
        float4 xv = *(const float4*)&Xb[(size_t)(k0+kk)*HW + p0 + pq];
        if (MODE == 2){
            float4 av = *(const float4*)&X2b[(size_t)(k0+kk)*HW + p0 + pq];
            xv.x*=av.x; xv.y*=av.y; xv.z*=av.z; xv.w*=av.w;
        }
        *(float4*)&Xs[kk][pq] = xv;
        __syncthreads();
        #pragma unroll
        for (int k = 0; k < 16; k++){
            float4 w4 = *(const float4*)&Ws[k][ty*4];
            float4 x4 = *(const float4*)&Xs[k][tx*4];
            acc[0][0]+=w4.x*x4.x; acc[0][1]+=w4.x*x4.y; acc[0][2]+=w4.x*x4.z; acc[0][3]+=w4.x*x4.w;
            acc[1][0]+=w4.y*x4.x; acc[1][1]+=w4.y*x4.y; acc[1][2]+=w4.y*x4.z; acc[1][3]+=w4.y*x4.w;
            acc[2][0]+=w4.z*x4.x; acc[2][1]+=w4.z*x4.y; acc[2][2]+=w4.z*x4.z; acc[2][3]+=w4.z*x4.w;
            acc[3][0]+=w4.w*x4.x; acc[3][1]+=w4.w*x4.y; acc[3][2]+=w4.w*x4.z; acc[3][3]+=w4.w*x4.w;
        }
        __syncthreads();
    }

    if (MODE == 0 || MODE == 1){
        #pragma unroll
        for (int i = 0; i < 4; i++){
            int co = co0 + ty*4 + i;
            float bv = bias[co];
            float4 r;
            r.x = acc[i][0]+bv; r.y = acc[i][1]+bv; r.z = acc[i][2]+bv; r.w = acc[i][3]+bv;
            if (MODE == 0){
                r.x = 0.5f*r.x*(1.0f+erff(r.x*0.70710678f));
                r.y = 0.5f*r.y*(1.0f+erff(r.y*0.70710678f));
                r.z = 0.5f*r.z*(1.0f+erff(r.z*0.70710678f));
                r.w = 0.5f*r.w*(1.0f+erff(r.w*0.70710678f));
            }
            *(float4*)&out[(size_t)b*C*HW + (size_t)co*HW + p0 + tx*4] = r;
        }
    } else {
        #pragma unroll
        for (int i = 0; i < 4; i++){
            int co = co0 + ty*4 + i;
            float bv = bias[co];
            float4 rv = *(const float4*)&res[(size_t)b*C*HW + (size_t)co*HW + p0 + tx*4];
            stage[tx*4+0][ty*4+i] = acc[i][0]+bv+rv.x;
            stage[tx*4+1][ty*4+i] = acc[i][1]+bv+rv.y;
            stage[tx*4+2][ty*4+i] = acc[i][2]+bv+rv.z;
            stage[tx*4+3][ty*4+i] = acc[i][3]+bv+rv.w;
        }
        __syncthreads();
        int pl = tid >> 2;
        int cq = (tid & 3) * 16;
        float* op = out + ((size_t)(b*HW + p0 + pl))*192 + co0 + cq;
        #pragma unroll
        for (int q = 0; q < 16; q += 4){
            float4 v;
            v.x = stage[pl][cq+q+0]; v.y = stage[pl][cq+q+1];
            v.z = stage[pl][cq+q+2]; v.w = stage[pl][cq+q+3];
            *(float4*)&op[q] = v;
        }
    }
}

// ---------------- depthwise 5x5 conv (NCHW), pad/dil params -----------------
__global__ void k_dw(const float* __restrict__ in, const float* __restrict__ w,
                     const float* __restrict__ bs, float* __restrict__ out,
                     int pad, int dil)
{
    int idx = blockIdx.x*256 + threadIdx.x;
    if (idx >= BATCH*C*HW) return;
    int x = idx & 127;
    int y = (idx >> 7) & 127;
    int plane = idx >> 14;             // b*C + c
    int c = plane % C;
    const float* ip = in + ((size_t)plane << 14);
    const float* wp = w + c*25;
    float s = bs[c];
    #pragma unroll
    for (int i = 0; i < 5; i++){
        int yy = y - pad + i*dil;
        if ((unsigned)yy < 128u){
            #pragma unroll
            for (int j = 0; j < 5; j++){
                int xx = x - pad + j*dil;
                if ((unsigned)xx < 128u)
                    s += wp[i*5+j] * ip[yy*128 + xx];
            }
        }
    }
    out[idx] = s;
}

// ---------------- LayerNorm over C for each pixel (BHWC in/out) -------------
__global__ void k_ln(const float* __restrict__ in, const float* __restrict__ g,
                     const float* __restrict__ bta, float* __restrict__ out)
{
    int gw = (blockIdx.x*blockDim.x + threadIdx.x) >> 5;
    int lane = threadIdx.x & 31;
    if (gw >= NPIX) return;
    const float* r = in + (size_t)gw*192;
    float v[6]; float s = 0.0f;
    #pragma unroll
    for (int t = 0; t < 6; t++){ v[t] = r[lane + 32*t]; s += v[t]; }
    #pragma unroll
    for (int o = 16; o > 0; o >>= 1) s += __shfl_xor_sync(0xffffffffu, s, o);
    float mu = s * (1.0f/192.0f);
    float q = 0.0f;
    #pragma unroll
    for (int t = 0; t < 6; t++){ float d = v[t]-mu; q += d*d; }
    #pragma unroll
    for (int o = 16; o > 0; o >>= 1) q += __shfl_xor_sync(0xffffffffu, q, o);
    float inv = rsqrtf(q * (1.0f/192.0f) + 1e-5f);
    float* w = out + (size_t)gw*192;
    #pragma unroll
    for (int t = 0; t < 6; t++){
        int c = lane + 32*t;
        w[c] = (v[t]-mu)*inv*g[c] + bta[c];
    }
}

// ---------------- row-major matmul: out[p][co] = X[p][:] . W[co][:] ---------
// MODE 0: qkv (N=576, +concat bias, out row-major [p][576])
// MODE 1: proj (N=192, +bias, out NCHW)
template<int MODE>
__global__ void k_mm(const float* __restrict__ Xg, const float* __restrict__ Wg,
                     const float* __restrict__ qb, const float* __restrict__ vb,
                     const float* __restrict__ pb, float* __restrict__ out)
{
    __shared__ float Xs[64][17];
    __shared__ float Wt[64][17];
    __shared__ float stage[64][65];
    const int tx = threadIdx.x, ty = threadIdx.y;
    const int tid = ty*16 + tx;
    const int co0 = blockIdx.x * 64;
    const int p0  = blockIdx.y * 64;
    float acc[4][4] = {};
    const int lr = tid >> 2;
    const int lk = (tid & 3) * 4;

    for (int k0 = 0; k0 < 192; k0 += 16){
        float4 xv = *(const float4*)&Xg[(size_t)(p0+lr)*192 + k0 + lk];
        Xs[lr][lk+0]=xv.x; Xs[lr][lk+1]=xv.y; Xs[lr][lk+2]=xv.z; Xs[lr][lk+3]=xv.w;
        float4 wv = *(const float4*)&Wg[(size_t)(co0+lr)*192 + k0 + lk];
        Wt[lr][lk+0]=wv.x; Wt[lr][lk+1]=wv.y; Wt[lr][lk+2]=wv.z; Wt[lr][lk+3]=wv.w;
        __syncthreads();
        #pragma unroll
        for (int k = 0; k < 16; k++){
            float xr[4], wr[4];
            #pragma unroll
            for (int j = 0; j < 4; j++) xr[j] = Xs[tx*4+j][k];
            #pragma unroll
            for (int i = 0; i < 4; i++) wr[i] = Wt[ty*4+i][k];
            #pragma unroll
            for (int i = 0; i < 4; i++)
                #pragma unroll
                for (int j = 0; j < 4; j++)
                    acc[i][j] += wr[i]*xr[j];
        }
        __syncthreads();
    }

    if (MODE == 0){
        #pragma unroll
        for (int i = 0; i < 4; i++){
            int co = co0 + ty*4 + i;
            float bv = (co < 192) ? qb[co] : (co < 384 ? 0.0f : vb[co-384]);
            #pragma unroll
            for (int j = 0; j < 4; j++)
                stage[tx*4+j][ty*4+i] = acc[i][j] + bv;
        }
        __syncthreads();
        int pl = tid >> 2;
        int cq = (tid & 3) * 16;
        float* op = out + (size_t)(p0+pl)*576 + co0 + cq;
        #pragma unroll
        for (int q = 0; q < 16; q += 4){
            float4 v;
            v.x = stage[pl][cq+q+0]; v.y = stage[pl][cq+q+1];
            v.z = stage[pl][cq+q+2]; v.w = stage[pl][cq+q+3];
            *(float4*)&op[q] = v;
        }
    } else {
        #pragma unroll
        for (int i = 0; i < 4; i++){
            int co = co0 + ty*4 + i;
            float bv = pb[co];
            int p = p0 + tx*4;
            int bb = p >> 14, hw = p & 16383;
            float4 v;
            v.x = acc[i][0]+bv; v.y = acc[i][1]+bv; v.z = acc[i][2]+bv; v.w = acc[i][3]+bv;
            *(float4*)&out[((size_t)bb*C + co)*HW + hw] = v;
        }
    }
}

// ---------------- SwinV2 cosine window attention ----------------------------
// grid: (window 0..255, head 0..5), 256 threads (one per query token)
__global__ void k_attn(const float* __restrict__ qkv, const float* __restrict__ tbl,
                       const float* __restrict__ lsc, float* __restrict__ out)
{
    extern __shared__ float sm[];
    float* kn = sm;              // 256*32
    float* vv = sm + 8192;       // 256*32
    float* sb = sm + 16384;      // 961
    const int w = blockIdx.x, h = blockIdx.y, i = threadIdx.x;
    const int b = w >> 6, wy = (w >> 3) & 7, wx = w & 7;
    const int iy = i >> 4, ix = i & 15;
    const size_t p_i = (size_t)b*HW + (size_t)(wy*16+iy)*128 + (wx*16+ix);

    // normalize + stage K, stage V
    {
        const float4* kr = (const float4*)(qkv + p_i*576 + 192 + h*32);
        const float4* vr = (const float4*)(qkv + p_i*576 + 384 + h*32);
        float4 kt[8]; float ss = 0.0f;
        #pragma unroll
        for (int d = 0; d < 8; d++){
            kt[d] = kr[d];
            ss += kt[d].x*kt[d].x + kt[d].y*kt[d].y + kt[d].z*kt[d].z + kt[d].w*kt[d].w;
        }
        float inv = 1.0f / fmaxf(sqrtf(ss), 1e-12f);
        float4* kd = (float4*)(kn + i*32);
        float4* vd = (float4*)(vv + i*32);
        #pragma unroll
        for (int d = 0; d < 8; d++){
            float4 t = kt[d]; t.x*=inv; t.y*=inv; t.z*=inv; t.w*=inv;
            kd[d] = t;
            vd[d] = vr[d];
        }
    }
    for (int t = i; t < 961; t += 256) sb[t] = tbl[t*6 + h];

    // normalized Q in registers
    float4 q[8];
    {
        const float4* qr = (const float4*)(qkv + p_i*576 + h*32);
        float ss = 0.0f;
        #pragma unroll
        for (int d = 0; d < 8; d++){
            q[d] = qr[d];
            ss += q[d].x*q[d].x + q[d].y*q[d].y + q[d].z*q[d].z + q[d].w*q[d].w;
        }
        float inv = 1.0f / fmaxf(sqrtf(ss), 1e-12f);
        #pragma unroll
        for (int d = 0; d < 8; d++){ q[d].x*=inv; q[d].y*=inv; q[d].z*=inv; q[d].w*=inv; }
    }
    const float scale = __expf(fminf(lsc[h], 4.6051702f));
    __syncthreads();

    float m = -1e30f, l = 0.0f;
    float4 o[8] = {};
    for (int c0 = 0; c0 < 256; c0 += 32){
        float s[32]; float cm = -1e30f;
        #pragma unroll
        for (int j = 0; j < 32; j++){
            const float4* kr = (const float4*)(kn + (c0+j)*32);
            float dot = 0.0f;
            #pragma unroll
            for (int d = 0; d < 8; d++){
                float4 kk = kr[d];
                dot += q[d].x*kk.x + q[d].y*kk.y + q[d].z*kk.z + q[d].w*kk.w;
            }
            int mm = c0 + j, my = mm >> 4, mx = mm & 15;
            float bias = sb[(iy-my+15)*31 + (ix-mx+15)];
            s[j] = fmaf(scale, dot, bias);
            cm = fmaxf(cm, s[j]);
        }
        float nm = fmaxf(m, cm);
        float corr = fexp(m - nm);
        l *= corr;
        #pragma unroll
        for (int d = 0; d < 8; d++){ o[d].x*=corr; o[d].y*=corr; o[d].z*=corr; o[d].w*=corr; }
        #pragma unroll
        for (int j = 0; j < 32; j++){
            float p = fexp(s[j] - nm);
            l += p;
            const float4* vr = (const float4*)(vv + (c0+j)*32);
            #pragma unroll
            for (int d = 0; d < 8; d++){
                float4 vk = vr[d];
                o[d].x = fmaf(p, vk.x, o[d].x);
                o[d].y = fmaf(p, vk.y, o[d].y);
                o[d].z = fmaf(p, vk.z, o[d].z);
                o[d].w = fmaf(p, vk.w, o[d].w);
            }
        }
        m = nm;
    }
    float inv = 1.0f / l;
    float4* op = (float4*)(out + p_i*192 + h*32);
    #pragma unroll
    for (int d = 0; d < 8; d++){
        float4 t = o[d]; t.x*=inv; t.y*=inv; t.z*=inv; t.w*=inv;
        op[d] = t;
    }
}

// ---------------------------------------------------------------------------
extern "C" void kernel_launch(void* const* d_in, const int* in_sizes, int n_in,
                              void* d_out, int out_size)
{
    const float* x      = (const float*)d_in[0];
    const float* p1_w   = (const float*)d_in[1];
    const float* p1_b   = (const float*)d_in[2];
    const float* pw_w   = (const float*)d_in[3];
    const float* pw_b   = (const float*)d_in[4];
    const float* dw_w   = (const float*)d_in[5];
    const float* dw_b   = (const float*)d_in[6];
    const float* dd_w   = (const float*)d_in[7];
    const float* dd_b   = (const float*)d_in[8];
    const float* p2_w   = (const float*)d_in[9];
    const float* p2_b   = (const float*)d_in[10];
    const float* ln_g   = (const float*)d_in[11];
    const float* ln_b   = (const float*)d_in[12];
    const float* qkv_w  = (const float*)d_in[13];
    const float* q_bias = (const float*)d_in[14];
    const float* v_bias = (const float*)d_in[15];
    const float* lsc    = (const float*)d_in[16];
    const float* cpb_w1 = (const float*)d_in[17];
    const float* cpb_b1 = (const float*)d_in[18];
    const float* cpb_w2 = (const float*)d_in[19];
    const float* proj_w = (const float*)d_in[20];
    const float* proj_b = (const float*)d_in[21];
    float* outp = (float*)d_out;

    float *gy, *ga, *gb, *gq, *gt;
    cudaGetSymbolAddress((void**)&gy, g_y);
    cudaGetSymbolAddress((void**)&ga, g_a);
    cudaGetSymbolAddress((void**)&gb, g_b);
    cudaGetSymbolAddress((void**)&gq, g_qkv);
    cudaGetSymbolAddress((void**)&gt, g_tbl);

    const int ATTN_SMEM = (8192 + 8192 + 961) * 4;
    cudaFuncSetAttribute(k_attn, cudaFuncAttributeMaxDynamicSharedMemorySize, ATTN_SMEM);

    dim3 blk(16, 16);
    dim3 gC(HW/64, C/64, BATCH);       // 256,3,4

    // CPB bias table (independent)
    k_cpb<<<961, 128>>>(cpb_w1, cpb_b1, cpb_w2, gt);

    // VAB conv block
    k_conv1x1<0><<<gC, blk>>>(x,  p1_w, p1_b, nullptr, nullptr, gy);   // y = gelu(p1 x)
    k_conv1x1<1><<<gC, blk>>>(gy, pw_w, pw_b, nullptr, nullptr, ga);   // a0 = pw y
    k_dw<<<(BATCH*C*HW)/256, 256>>>(ga, dw_w, dw_b, gb, 2, 1);         // a1 = dw 5x5
    k_dw<<<(BATCH*C*HW)/256, 256>>>(gb, dd_w, dd_b, ga, 6, 3);         // a2 = dw 5x5 dil3
    k_conv1x1<2><<<gC, blk>>>(gy, p2_w, p2_b, ga, x, gb);              // BHWC: p2(y*a2)+x

    // LayerNorm
    k_ln<<<NPIX/8, 256>>>(gb, ln_g, ln_b, gy);                         // gy = yln (BHWC)

    // QKV projection
    k_mm<0><<<dim3(9, NPIX/64), blk>>>(gy, qkv_w, q_bias, v_bias, nullptr, gq);

    // Windowed cosine attention -> BHWC in ga
    k_attn<<<dim3(NWIN, NH), 256, ATTN_SMEM>>>(gq, gt, lsc, ga);

    // Output projection -> NCHW d_out
    k_mm<1><<<dim3(3, NPIX/64), blk>>>(ga, proj_w, nullptr, nullptr, proj_b, outp);
}

// round 2
// speedup vs baseline: 1.1438x; 1.1438x over previous
#include <cuda_runtime.h>
#include <math.h>

#define BATCH 4
#define C 192
#define HW 16384            // 128*128
#define NPIX (BATCH*HW)     // 65536
#define NH 6
#define HD 32
#define NWIN 256
#define NTOK 256

// ---------------- scratch (device globals; no allocations allowed) ----------
__device__ float g_y[BATCH*C*HW];
__device__ float g_a[BATCH*C*HW];
__device__ float g_b[BATCH*C*HW];
__device__ float g_qkv[(size_t)NPIX*576];
__device__ float g_tbl[961*NH];

// ---------------- fast exp on the FMA pipe ---------------------------------
__device__ __forceinline__ float fexp(float x){
    float z  = fmaxf(x * 1.44269504088896f, -126.0f);
    float mz = z + 12582912.0f;
    int   iz = __float_as_int(mz);
    float zi = mz - 12582912.0f;
    float f  = z - zi;
    float p  = 1.0f + f*(0.6931471806f + f*(0.2402265070f + f*(0.0555041087f
              + f*(0.0096181291f + f*0.0013333558f))));
    return __int_as_float(__float_as_int(p) + (iz << 23));
}

// ---------------- CPB MLP table --------------------------------------------
__global__ void k_cpb(const float* __restrict__ w1, const float* __restrict__ b1,
                      const float* __restrict__ w2, float* __restrict__ tbl)
{
    int r = blockIdx.x;
    int t = threadIdx.x;
    float dy = (float)(r / 31) - 15.0f;
    float dx = (float)(r % 31) - 15.0f;
    float u0 = dy / 15.0f * 8.0f, u1 = dx / 15.0f * 8.0f;
    float t0 = copysignf(log2f(fabsf(u0) + 1.0f) * (1.0f/3.0f), u0);
    float t1 = copysignf(log2f(fabsf(u1) + 1.0f) * (1.0f/3.0f), u1);
    float acc[6] = {0,0,0,0,0,0};
    for (int u = t; u < 512; u += 128){
        float hv = fmaxf(w1[2*u]*t0 + w1[2*u+1]*t1 + b1[u], 0.0f);
        #pragma unroll
        for (int h = 0; h < 6; h++) acc[h] += hv * w2[h*512 + u];
    }
    __shared__ float red[6][128];
    #pragma unroll
    for (int h = 0; h < 6; h++) red[h][t] = acc[h];
    __syncthreads();
    for (int off = 64; off > 0; off >>= 1){
        if (t < off){
            #pragma unroll
            for (int h = 0; h < 6; h++) red[h][t] += red[h][t+off];
        }
        __syncthreads();
    }
    if (t < 6){
        float v = red[t][0];
        tbl[r*6 + t] = 16.0f / (1.0f + expf(-v));
    }
}

// ---------------- 1x1 conv (NCHW input): 64co x 256p tile, 8x8/thread -------
// MODE 0: +bias, GELU, write NCHW      (p1)
// MODE 1: +bias, write NCHW            (pw)
// MODE 2: X := X .* X2, +bias +res(x), write BHWC (p2 + residual)
template<int MODE>
__global__ void __launch_bounds__(256)
k_conv1x1(const float* __restrict__ X, const float* __restrict__ Wg,
          const float* __restrict__ bias, const float* __restrict__ X2,
          const float* __restrict__ res, float* __restrict__ out)
{
    __shared__ float Ws[16][68];
    __shared__ float Xs[16][260];

    const int t  = threadIdx.x;
    const int p0 = blockIdx.x * 256;
    const int co0 = blockIdx.y * 64;
    const int b  = blockIdx.z;
    const float* Xb  = X + (size_t)b*C*HW;
    const float* X2b = (MODE==2) ? (X2 + (size_t)b*C*HW) : nullptr;

    const int tx = t & 31;      // p group (8 each)
    const int ty = t >> 5;      // co group (8 each)

    // W loader: thread t loads float4 along k for co = t>>2
    const int wco = t >> 2;
    const int wkq = (t & 3) * 4;
    // X loader: kk = t>>6 + r*4, pq = (t&63)*4
    const int xk0 = t >> 6;
    const int xq  = (t & 63) * 4;

    float acc[8][8] = {};

    for (int k0 = 0; k0 < 192; k0 += 16){
        float4 wv = *(const float4*)&Wg[(size_t)(co0+wco)*192 + k0 + wkq];
        Ws[wkq+0][wco]=wv.x; Ws[wkq+1][wco]=wv.y; Ws[wkq+2][wco]=wv.z; Ws[wkq+3][wco]=wv.w;
        #pragma unroll
        for (int r = 0; r < 4; r++){
            int kk = xk0 + r*4;
            float4 xv = *(const float4*)&Xb[(size_t)(k0+kk)*HW + p0 + xq];
            if (MODE == 2){
                float4 av = *(const float4*)&X2b[(size_t)(k0+kk)*HW + p0 + xq];
                xv.x*=av.x; xv.y*=av.y; xv.z*=av.z; xv.w*=av.w;
            }
            *(float4*)&Xs[kk][xq] = xv;
        }
        __syncthreads();
        #pragma unroll
        for (int k = 0; k < 16; k++){
            float wr[8], xr[8];
            *(float4*)&wr[0] = *(const float4*)&Ws[k][ty*8];
            *(float4*)&wr[4] = *(const float4*)&Ws[k][ty*8+4];
            *(float4*)&xr[0] = *(const float4*)&Xs[k][tx*8];
            *(float4*)&xr[4] = *(const float4*)&Xs[k][tx*8+4];
            #pragma unroll
            for (int i = 0; i < 8; i++)
                #pragma unroll
                for (int j = 0; j < 8; j++)
                    acc[i][j] = fmaf(wr[i], xr[j], acc[i][j]);
        }
        __syncthreads();
    }

    if (MODE == 0 || MODE == 1){
        #pragma unroll
        for (int i = 0; i < 8; i++){
            int co = co0 + ty*8 + i;
            float bv = bias[co];
            float v[8];
            #pragma unroll
            for (int j = 0; j < 8; j++){
                float r = acc[i][j] + bv;
                if (MODE == 0) r = 0.5f*r*(1.0f+erff(r*0.70710678f));
                v[j] = r;
            }
            float* op = &out[(size_t)b*C*HW + (size_t)co*HW + p0 + tx*8];
            *(float4*)&op[0] = *(float4*)&v[0];
            *(float4*)&op[4] = *(float4*)&v[4];
        }
    } else {
        // + residual (NCHW), write BHWC
        float rv[8][8];
        #pragma unroll
        for (int i = 0; i < 8; i++){
            int co = co0 + ty*8 + i;
            const float* rp = &res[(size_t)b*C*HW + (size_t)co*HW + p0 + tx*8];
            *(float4*)&rv[i][0] = *(const float4*)&rp[0];
            *(float4*)&rv[i][4] = *(const float4*)&rp[4];
        }
        #pragma unroll
        for (int j = 0; j < 8; j++){
            int p = p0 + tx*8 + j;
            float v[8];
            #pragma unroll
            for (int i = 0; i < 8; i++)
                v[i] = acc[i][j] + bias[co0+ty*8+i] + rv[i][j];
            float* op = &out[((size_t)(b*HW) + p)*192 + co0 + ty*8];
            *(float4*)&op[0] = *(float4*)&v[0];
            *(float4*)&op[4] = *(float4*)&v[4];
        }
    }
}

// ---------------- fused depthwise 5x5 + 5x5 dil3 ----------------------------
__global__ void __launch_bounds__(256)
k_dwf(const float* __restrict__ in, const float* __restrict__ w1,
      const float* __restrict__ b1, const float* __restrict__ w2,
      const float* __restrict__ b2, float* __restrict__ out)
{
    __shared__ float s0[48][49];
    __shared__ float s1[44][45];
    __shared__ float wts[52];
    const int plane = blockIdx.y;          // b*C + c
    const int c = plane % C;
    const int tile = blockIdx.x;           // 0..15
    const int y0 = (tile >> 2) * 32, x0 = (tile & 3) * 32;
    const int t = threadIdx.x;

    if (t < 25) wts[t] = w1[c*25 + t];
    else if (t < 50) wts[t] = w2[c*25 + t - 25];
    else if (t == 50) wts[50] = b1[c];
    else if (t == 51) wts[51] = b2[c];

    const float* ip = in + ((size_t)plane << 14);
    for (int idx = t; idx < 48*48; idx += 256){
        int yy = idx / 48, xx = idx - yy*48;
        int gy = y0 - 8 + yy, gx = x0 - 8 + xx;
        s0[yy][xx] = ((unsigned)gy < 128u && (unsigned)gx < 128u) ? ip[gy*128+gx] : 0.0f;
    }
    __syncthreads();

    for (int idx = t; idx < 44*44; idx += 256){
        int r = idx / 44, cc = idx - r*44;
        int gy = y0 - 6 + r, gx = x0 - 6 + cc;
        float v = 0.0f;
        if ((unsigned)gy < 128u && (unsigned)gx < 128u){
            v = wts[50];
            #pragma unroll
            for (int i = 0; i < 5; i++)
                #pragma unroll
                for (int j = 0; j < 5; j++)
                    v = fmaf(wts[i*5+j], s0[r+i][cc+j], v);
        }
        s1[r][cc] = v;
    }
    __syncthreads();

    for (int idx = t; idx < 1024; idx += 256){
        int r = idx >> 5, cc = idx & 31;
        float v = wts[51];
        #pragma unroll
        for (int i = 0; i < 5; i++)
            #pragma unroll
            for (int j = 0; j < 5; j++)
                v = fmaf(wts[25+i*5+j], s1[r+3*i][cc+3*j], v);
        out[((size_t)plane << 14) + (y0+r)*128 + x0 + cc] = v;
    }
}

// ---------------- LayerNorm over C per pixel (BHWC) -------------------------
__global__ void k_ln(const float* __restrict__ in, const float* __restrict__ g,
                     const float* __restrict__ bta, float* __restrict__ out)
{
    int gw = (blockIdx.x*blockDim.x + threadIdx.x) >> 5;
    int lane = threadIdx.x & 31;
    if (gw >= NPIX) return;
    const float* r = in + (size_t)gw*192;
    float v[6]; float s = 0.0f;
    #pragma unroll
    for (int t = 0; t < 6; t++){ v[t] = r[lane + 32*t]; s += v[t]; }
    #pragma unroll
    for (int o = 16; o > 0; o >>= 1) s += __shfl_xor_sync(0xffffffffu, s, o);
    float mu = s * (1.0f/192.0f);
    float q = 0.0f;
    #pragma unroll
    for (int t = 0; t < 6; t++){ float d = v[t]-mu; q += d*d; }
    #pragma unroll
    for (int o = 16; o > 0; o >>= 1) q += __shfl_xor_sync(0xffffffffu, q, o);
    float inv = rsqrtf(q * (1.0f/192.0f) + 1e-5f);
    float* w = out + (size_t)gw*192;
    #pragma unroll
    for (int t = 0; t < 6; t++){
        int c = lane + 32*t;
        w[c] = (v[t]-mu)*inv*g[c] + bta[c];
    }
}

// ---------------- row-major matmul: out[p][co] = X[p][:].W[co][:] -----------
// 64co x 256p tile, 8x8/thread. MODE 0: qkv (+concat bias, out [p][576])
//                               MODE 1: proj (+bias, out NCHW)
template<int MODE>
__global__ void __launch_bounds__(256)
k_mm(const float* __restrict__ Xg, const float* __restrict__ Wg,
     const float* __restrict__ qb, const float* __restrict__ vb,
     const float* __restrict__ pb, float* __restrict__ out)
{
    __shared__ float Ws[16][68];
    __shared__ float Xs[16][260];
    const int t = threadIdx.x;
    const int co0 = blockIdx.x * 64;
    const int p0  = blockIdx.y * 256;
    const int tx = t & 31;
    const int ty = t >> 5;

    const int wco = t >> 2;
    const int wkq = (t & 3) * 4;
    const int xpl = t >> 2;         // 0..63
    const int xkq = (t & 3) * 4;

    float acc[8][8] = {};

    for (int k0 = 0; k0 < 192; k0 += 16){
        float4 wv = *(const float4*)&Wg[(size_t)(co0+wco)*192 + k0 + wkq];
        Ws[wkq+0][wco]=wv.x; Ws[wkq+1][wco]=wv.y; Ws[wkq+2][wco]=wv.z; Ws[wkq+3][wco]=wv.w;
        #pragma unroll
        for (int r = 0; r < 4; r++){
            int pl = xpl + r*64;
            float4 xv = *(const float4*)&Xg[(size_t)(p0+pl)*192 + k0 + xkq];
            Xs[xkq+0][pl]=xv.x; Xs[xkq+1][pl]=xv.y; Xs[xkq+2][pl]=xv.z; Xs[xkq+3][pl]=xv.w;
        }
        __syncthreads();
        #pragma unroll
        for (int k = 0; k < 16; k++){
            float wr[8], xr[8];
            *(float4*)&wr[0] = *(const float4*)&Ws[k][ty*8];
            *(float4*)&wr[4] = *(const float4*)&Ws[k][ty*8+4];
            *(float4*)&xr[0] = *(const float4*)&Xs[k][tx*8];
            *(float4*)&xr[4] = *(const float4*)&Xs[k][tx*8+4];
            #pragma unroll
            for (int i = 0; i < 8; i++)
                #pragma unroll
                for (int j = 0; j < 8; j++)
                    acc[i][j] = fmaf(wr[i], xr[j], acc[i][j]);
        }
        __syncthreads();
    }

    if (MODE == 0){
        float bv[8];
        #pragma unroll
        for (int i = 0; i < 8; i++){
            int co = co0 + ty*8 + i;
            bv[i] = (co < 192) ? qb[co] : (co < 384 ? 0.0f : vb[co-384]);
        }
        #pragma unroll
        for (int j = 0; j < 8; j++){
            int p = p0 + tx*8 + j;
            float v[8];
            #pragma unroll
            for (int i = 0; i < 8; i++) v[i] = acc[i][j] + bv[i];
            float* op = &out[(size_t)p*576 + co0 + ty*8];
            *(float4*)&op[0] = *(float4*)&v[0];
            *(float4*)&op[4] = *(float4*)&v[4];
        }
    } else {
        #pragma unroll
        for (int i = 0; i < 8; i++){
            int co = co0 + ty*8 + i;
            float bv = pb[co];
            int p = p0 + tx*8;
            int bb = p >> 14, hw = p & 16383;
            float v[8];
            #pragma unroll
            for (int j = 0; j < 8; j++) v[j] = acc[i][j] + bv;
            float* op = &out[((size_t)bb*C + co)*HW + hw];
            *(float4*)&op[0] = *(float4*)&v[0];
            *(float4*)&op[4] = *(float4*)&v[4];
        }
    }
}

// ---------------- SwinV2 cosine window attention ----------------------------
__global__ void k_attn(const float* __restrict__ qkv, const float* __restrict__ tbl,
                       const float* __restrict__ lsc, float* __restrict__ out)
{
    extern __shared__ float sm[];
    float* kn = sm;
    float* vv = sm + 8192;
    float* sb = sm + 16384;
    const int w = blockIdx.x, h = blockIdx.y, i = threadIdx.x;
    const int b = w >> 6, wy = (w >> 3) & 7, wx = w & 7;
    const int iy = i >> 4, ix = i & 15;
    const size_t p_i = (size_t)b*HW + (size_t)(wy*16+iy)*128 + (wx*16+ix);

    {
        const float4* kr = (const float4*)(qkv + p_i*576 + 192 + h*32);
        const float4* vr = (const float4*)(qkv + p_i*576 + 384 + h*32);
        float4 kt[8]; float ss = 0.0f;
        #pragma unroll
        for (int d = 0; d < 8; d++){
            kt[d] = kr[d];
            ss += kt[d].x*kt[d].x + kt[d].y*kt[d].y + kt[d].z*kt[d].z + kt[d].w*kt[d].w;
        }
        float inv = 1.0f / fmaxf(sqrtf(ss), 1e-12f);
        float4* kd = (float4*)(kn + i*32);
        float4* vd = (float4*)(vv + i*32);
        #pragma unroll
        for (int d = 0; d < 8; d++){
            float4 tt = kt[d]; tt.x*=inv; tt.y*=inv; tt.z*=inv; tt.w*=inv;
            kd[d] = tt;
            vd[d] = vr[d];
        }
    }
    for (int t = i; t < 961; t += 256) sb[t] = tbl[t*6 + h];

    float4 q[8];
    {
        const float4* qr = (const float4*)(qkv + p_i*576 + h*32);
        float ss = 0.0f;
        #pragma unroll
        for (int d = 0; d < 8; d++){
            q[d] = qr[d];
            ss += q[d].x*q[d].x + q[d].y*q[d].y + q[d].z*q[d].z + q[d].w*q[d].w;
        }
        float inv = 1.0f / fmaxf(sqrtf(ss), 1e-12f);
        #pragma unroll
        for (int d = 0; d < 8; d++){ q[d].x*=inv; q[d].y*=inv; q[d].z*=inv; q[d].w*=inv; }
    }
    const float scale = __expf(fminf(lsc[h], 4.6051702f));
    __syncthreads();

    float m = -1e30f, l = 0.0f;
    float4 o[8] = {};
    for (int c0 = 0; c0 < 256; c0 += 32){
        float s[32]; float cm = -1e30f;
        #pragma unroll
        for (int j = 0; j < 32; j++){
            const float4* kr = (const float4*)(kn + (c0+j)*32);
            float dot = 0.0f;
            #pragma unroll
            for (int d = 0; d < 8; d++){
                float4 kk = kr[d];
                dot += q[d].x*kk.x + q[d].y*kk.y + q[d].z*kk.z + q[d].w*kk.w;
            }
            int mm = c0 + j, my = mm >> 4, mx = mm & 15;
            float bias = sb[(iy-my+15)*31 + (ix-mx+15)];
            s[j] = fmaf(scale, dot, bias);
            cm = fmaxf(cm, s[j]);
        }
        float nm = fmaxf(m, cm);
        float corr = fexp(m - nm);
        l *= corr;
        #pragma unroll
        for (int d = 0; d < 8; d++){ o[d].x*=corr; o[d].y*=corr; o[d].z*=corr; o[d].w*=corr; }
        #pragma unroll
        for (int j = 0; j < 32; j++){
            float p = fexp(s[j] - nm);
            l += p;
            const float4* vr = (const float4*)(vv + (c0+j)*32);
            #pragma unroll
            for (int d = 0; d < 8; d++){
                float4 vk = vr[d];
                o[d].x = fmaf(p, vk.x, o[d].x);
                o[d].y = fmaf(p, vk.y, o[d].y);
                o[d].z = fmaf(p, vk.z, o[d].z);
                o[d].w = fmaf(p, vk.w, o[d].w);
            }
        }
        m = nm;
    }
    float inv = 1.0f / l;
    float4* op = (float4*)(out + p_i*192 + h*32);
    #pragma unroll
    for (int d = 0; d < 8; d++){
        float4 tt = o[d]; tt.x*=inv; tt.y*=inv; tt.z*=inv; tt.w*=inv;
        op[d] = tt;
    }
}

// ---------------------------------------------------------------------------
extern "C" void kernel_launch(void* const* d_in, const int* in_sizes, int n_in,
                              void* d_out, int out_size)
{
    const float* x      = (const float*)d_in[0];
    const float* p1_w   = (const float*)d_in[1];
    const float* p1_b   = (const float*)d_in[2];
    const float* pw_w   = (const float*)d_in[3];
    const float* pw_b   = (const float*)d_in[4];
    const float* dw_w   = (const float*)d_in[5];
    const float* dw_b   = (const float*)d_in[6];
    const float* dd_w   = (const float*)d_in[7];
    const float* dd_b   = (const float*)d_in[8];
    const float* p2_w   = (const float*)d_in[9];
    const float* p2_b   = (const float*)d_in[10];
    const float* ln_g   = (const float*)d_in[11];
    const float* ln_b   = (const float*)d_in[12];
    const float* qkv_w  = (const float*)d_in[13];
    const float* q_bias = (const float*)d_in[14];
    const float* v_bias = (const float*)d_in[15];
    const float* lsc    = (const float*)d_in[16];
    const float* cpb_w1 = (const float*)d_in[17];
    const float* cpb_b1 = (const float*)d_in[18];
    const float* cpb_w2 = (const float*)d_in[19];
    const float* proj_w = (const float*)d_in[20];
    const float* proj_b = (const float*)d_in[21];
    float* outp = (float*)d_out;

    float *gy, *ga, *gb, *gq, *gt;
    cudaGetSymbolAddress((void**)&gy, g_y);
    cudaGetSymbolAddress((void**)&ga, g_a);
    cudaGetSymbolAddress((void**)&gb, g_b);
    cudaGetSymbolAddress((void**)&gq, g_qkv);
    cudaGetSymbolAddress((void**)&gt, g_tbl);

    const int ATTN_SMEM = (8192 + 8192 + 961) * 4;
    cudaFuncSetAttribute(k_attn, cudaFuncAttributeMaxDynamicSharedMemorySize, ATTN_SMEM);

    dim3 gC(HW/256, C/64, BATCH);      // 64,3,4

    // CPB bias table (independent)
    k_cpb<<<961, 128>>>(cpb_w1, cpb_b1, cpb_w2, gt);

    // VAB conv block
    k_conv1x1<0><<<gC, 256>>>(x,  p1_w, p1_b, nullptr, nullptr, gy);    // y = gelu(p1 x)
    k_conv1x1<1><<<gC, 256>>>(gy, pw_w, pw_b, nullptr, nullptr, ga);    // a0 = pw y
    k_dwf<<<dim3(16, BATCH*C), 256>>>(ga, dw_w, dw_b, dd_w, dd_b, gb);  // a2 = dd(dw(a0))
    k_conv1x1<2><<<gC, 256>>>(gy, p2_w, p2_b, gb, x, ga);               // BHWC: p2(y*a2)+x

    // LayerNorm
    k_ln<<<NPIX/8, 256>>>(ga, ln_g, ln_b, gy);                          // gy = yln (BHWC)

    // QKV projection
    k_mm<0><<<dim3(9, NPIX/256), 256>>>(gy, qkv_w, q_bias, v_bias, nullptr, gq);

    // Windowed cosine attention -> BHWC in ga
    k_attn<<<dim3(NWIN, NH), 256, ATTN_SMEM>>>(gq, gt, lsc, ga);

    // Output projection -> NCHW d_out
    k_mm<1><<<dim3(3, NPIX/256), 256>>>(ga, proj_w, nullptr, nullptr, proj_b, outp);
}

// round 3
// speedup vs baseline: 1.5940x; 1.3937x over previous
#include <cuda_runtime.h>
#include <cuda_bf16.h>
#include <math.h>

#define BATCH 4
#define C 192
#define HW 16384            // 128*128
#define NPIX (BATCH*HW)     // 65536
#define NH 6
#define HD 32
#define NWIN 256
#define NTOK 256

// ---------------- scratch (device globals; no allocations allowed) ----------
__device__ float g_y[BATCH*C*HW];
__device__ float g_a[BATCH*C*HW];
__device__ float g_b[BATCH*C*HW];
__device__ float g_qkv[(size_t)NPIX*576];
__device__ float g_tbl[961*NH];

// ---------------- fast exp on the FMA pipe ---------------------------------
__device__ __forceinline__ float fexp(float x){
    float z  = fmaxf(x * 1.44269504088896f, -126.0f);
    float mz = z + 12582912.0f;
    int   iz = __float_as_int(mz);
    float zi = mz - 12582912.0f;
    float f  = z - zi;
    float p  = 1.0f + f*(0.6931471806f + f*(0.2402265070f + f*(0.0555041087f
              + f*(0.0096181291f + f*0.0013333558f))));
    return __int_as_float(__float_as_int(p) + (iz << 23));
}

// ---------------- bf16 split helpers ---------------------------------------
__device__ __forceinline__ unsigned packbf(float lo, float hi){
    unsigned r;
    asm("cvt.rn.bf16x2.f32 %0, %1, %2;" : "=r"(r) : "f"(hi), "f"(lo));
    return r;
}
__device__ __forceinline__ float bflo(unsigned u){ return __uint_as_float(u << 16); }
__device__ __forceinline__ float bfhi(unsigned u){ return __uint_as_float(u & 0xffff0000u); }

// split a pair (lo-k, hi-k) into hi-plane packed + lo-plane packed
__device__ __forceinline__ void split2(float a, float b, unsigned& h, unsigned& l){
    h = packbf(a, b);
    l = packbf(a - bflo(h), b - bfhi(h));
}

__device__ __forceinline__ void mma_bf16(float c[4], const unsigned a[4],
                                         unsigned b0, unsigned b1){
    asm("mma.sync.aligned.m16n8k16.row.col.f32.bf16.bf16.f32 "
        "{%0,%1,%2,%3},{%4,%5,%6,%7},{%8,%9},{%0,%1,%2,%3};"
        : "+f"(c[0]), "+f"(c[1]), "+f"(c[2]), "+f"(c[3])
        : "r"(a[0]), "r"(a[1]), "r"(a[2]), "r"(a[3]), "r"(b0), "r"(b1));
}

// ---------------- CPB MLP table --------------------------------------------
__global__ void k_cpb(const float* __restrict__ w1, const float* __restrict__ b1,
                      const float* __restrict__ w2, float* __restrict__ tbl)
{
    int r = blockIdx.x;
    int t = threadIdx.x;
    float dy = (float)(r / 31) - 15.0f;
    float dx = (float)(r % 31) - 15.0f;
    float u0 = dy / 15.0f * 8.0f, u1 = dx / 15.0f * 8.0f;
    float t0 = copysignf(log2f(fabsf(u0) + 1.0f) * (1.0f/3.0f), u0);
    float t1 = copysignf(log2f(fabsf(u1) + 1.0f) * (1.0f/3.0f), u1);
    float acc[6] = {0,0,0,0,0,0};
    for (int u = t; u < 512; u += 128){
        float hv = fmaxf(w1[2*u]*t0 + w1[2*u+1]*t1 + b1[u], 0.0f);
        #pragma unroll
        for (int h = 0; h < 6; h++) acc[h] += hv * w2[h*512 + u];
    }
    __shared__ float red[6][128];
    #pragma unroll
    for (int h = 0; h < 6; h++) red[h][t] = acc[h];
    __syncthreads();
    for (int off = 64; off > 0; off >>= 1){
        if (t < off){
            #pragma unroll
            for (int h = 0; h < 6; h++) red[h][t] += red[h][t+off];
        }
        __syncthreads();
    }
    if (t < 6){
        float v = red[t][0];
        tbl[r*6 + t] = 16.0f / (1.0f + expf(-v));
    }
}

// ---------------- tensor-core GEMM (bf16 hi/lo split, fp32 accum) ----------
// out[co][p] = sum_k W[co][k] * X[k][p]   (per mode's data layout)
// Block tile 64(co) x 256(p), K-chunk 32. 8 warps: 2(M) x 4(N), warp 32x64.
// MODE 0: p1  : X NCHW, +bias, GELU -> NCHW
// MODE 1: pw  : X NCHW, +bias      -> NCHW
// MODE 2: p2  : X NCHW * X2 NCHW, +bias +res(NCHW) -> BHWC
// MODE 3: qkv : X row-major [p][192], concat bias -> [p][576]
// MODE 4: proj: X row-major [p][192], +bias -> NCHW
template<int MODE>
__global__ void __launch_bounds__(256, 2)
k_gemm(const float* __restrict__ X, const float* __restrict__ W,
       const float* __restrict__ bias, const float* __restrict__ X2,
       const float* __restrict__ res, const float* __restrict__ qb,
       const float* __restrict__ vb, float* __restrict__ out)
{
    extern __shared__ unsigned smem_u[];
    unsigned* Ah = smem_u;                  // 64*20
    unsigned* Al = Ah + 64*20;
    unsigned* Bh = Al + 64*20;              // 16*260
    unsigned* Bl = Bh + 16*260;
    float* stg = (float*)smem_u;            // overlay (modes 2,3): 64*260 floats

    const int t = threadIdx.x;
    const int wid = t >> 5, lane = t & 31;
    const int gid = lane >> 2, tig = lane & 3;
    const int m0w = (wid & 1) * 32;
    const int n0w = (wid >> 1) * 64;

    const int p0  = blockIdx.x * 256;       // pixel offset (within batch for NCHW modes)
    const int co0 = blockIdx.y * 64;
    const int bz  = (MODE <= 2) ? blockIdx.z : 0;

    const float* Xb  = (MODE <= 2) ? (X + (size_t)bz*C*HW) : X;
    const float* X2b = (MODE == 2) ? (X2 + (size_t)bz*C*HW) : nullptr;

    float c[2][8][4];
    #pragma unroll
    for (int i = 0; i < 2; i++)
        #pragma unroll
        for (int j = 0; j < 8; j++)
            #pragma unroll
            for (int q = 0; q < 4; q++) c[i][j][q] = 0.0f;

    // loader indices
    const int ar  = t >> 2;                 // A row 0..63
    const int akq = (t & 3) * 8;            // A k offset (8 values)

    for (int kc = 0; kc < 6; kc++){
        const int k0 = kc * 32;
        __syncthreads();
        // ---- A: W[co0+ar][k0+akq .. +8] -> Ah/Al [ar][akq/2 ..]
        {
            const float* wp = &W[(size_t)(co0 + ar)*192 + k0 + akq];
            float4 w0 = *(const float4*)wp;
            float4 w1 = *(const float4*)(wp + 4);
            uint4 h, l;
            split2(w0.x, w0.y, h.x, l.x);
            split2(w0.z, w0.w, h.y, l.y);
            split2(w1.x, w1.y, h.z, l.z);
            split2(w1.z, w1.w, h.w, l.w);
            *(uint4*)&Ah[ar*20 + akq/2] = h;
            *(uint4*)&Al[ar*20 + akq/2] = l;
        }
        // ---- B
        if (MODE <= 2){
            const int bp  = (t & 63) * 4;
            const int bk2 = t >> 6;         // 0..3
            #pragma unroll
            for (int r = 0; r < 4; r++){
                int k2i = bk2 + r*4;        // 0..15
                int k = k0 + k2i*2;
                const float* xr = Xb + (size_t)k*HW + p0 + bp;
                float4 e = *(const float4*)xr;
                float4 o = *(const float4*)(xr + HW);
                if (MODE == 2){
                    const float* mr = X2b + (size_t)k*HW + p0 + bp;
                    float4 m1 = *(const float4*)mr;
                    float4 m2 = *(const float4*)(mr + HW);
                    e.x*=m1.x; e.y*=m1.y; e.z*=m1.z; e.w*=m1.w;
                    o.x*=m2.x; o.y*=m2.y; o.z*=m2.z; o.w*=m2.w;
                }
                uint4 h, l;
                split2(e.x, o.x, h.x, l.x);
                split2(e.y, o.y, h.y, l.y);
                split2(e.z, o.z, h.z, l.z);
                split2(e.w, o.w, h.w, l.w);
                *(uint4*)&Bh[k2i*260 + bp] = h;
                *(uint4*)&Bl[k2i*260 + bp] = l;
            }
        } else {
            const int fi = t & 7;
            const int k = k0 + fi*4;
            #pragma unroll
            for (int r = 0; r < 8; r++){
                int pl = (t >> 3) + r*32;
                float4 v = *(const float4*)&Xb[(size_t)(p0 + pl)*192 + k];
                unsigned h0, l0, h1, l1;
                split2(v.x, v.y, h0, l0);
                split2(v.z, v.w, h1, l1);
                Bh[(fi*2  )*260 + pl] = h0;
                Bh[(fi*2+1)*260 + pl] = h1;
                Bl[(fi*2  )*260 + pl] = l0;
                Bl[(fi*2+1)*260 + pl] = l1;
            }
        }
        __syncthreads();

        // ---- compute: 2 k16-steps
        #pragma unroll
        for (int ks = 0; ks < 2; ks++){
            const int kb = ks * 8;
            unsigned ah[2][4], al2[2][4];
            #pragma unroll
            for (int mt = 0; mt < 2; mt++){
                int mr = m0w + mt*16 + gid;
                ah[mt][0]  = Ah[mr*20 + kb + tig];
                ah[mt][1]  = Ah[(mr+8)*20 + kb + tig];
                ah[mt][2]  = Ah[mr*20 + kb + tig + 4];
                ah[mt][3]  = Ah[(mr+8)*20 + kb + tig + 4];
                al2[mt][0] = Al[mr*20 + kb + tig];
                al2[mt][1] = Al[(mr+8)*20 + kb + tig];
                al2[mt][2] = Al[mr*20 + kb + tig + 4];
                al2[mt][3] = Al[(mr+8)*20 + kb + tig + 4];
            }
            #pragma unroll
            for (int nt = 0; nt < 8; nt++){
                int nn = n0w + nt*8 + gid;
                unsigned bh0 = Bh[(kb+tig  )*260 + nn];
                unsigned bh1 = Bh[(kb+tig+4)*260 + nn];
                unsigned bl0 = Bl[(kb+tig  )*260 + nn];
                unsigned bl1 = Bl[(kb+tig+4)*260 + nn];
                #pragma unroll
                for (int mt = 0; mt < 2; mt++){
                    mma_bf16(c[mt][nt], ah[mt],  bh0, bh1);
                    mma_bf16(c[mt][nt], ah[mt],  bl0, bl1);
                    mma_bf16(c[mt][nt], al2[mt], bh0, bh1);
                }
            }
        }
    }

    // ---- epilogue ----
    if (MODE == 0 || MODE == 1){
        #pragma unroll
        for (int mt = 0; mt < 2; mt++){
            #pragma unroll
            for (int s = 0; s < 2; s++){
                int rl = m0w + mt*16 + gid + s*8;
                float bv = bias[co0 + rl];
                float* orow = out + ((size_t)bz*C + co0 + rl)*HW + p0;
                #pragma unroll
                for (int nt = 0; nt < 8; nt++){
                    int cs = n0w + nt*8 + tig*2;
                    float v0 = c[mt][nt][s*2+0] + bv;
                    float v1 = c[mt][nt][s*2+1] + bv;
                    if (MODE == 0){
                        v0 = 0.5f*v0*(1.0f + erff(v0*0.70710678f));
                        v1 = 0.5f*v1*(1.0f + erff(v1*0.70710678f));
                    }
                    float2 v = {v0, v1};
                    *(float2*)&orow[cs] = v;
                }
            }
        }
    } else if (MODE == 4){
        const int bb = p0 >> 14;
        const int hw0 = p0 & 16383;
        #pragma unroll
        for (int mt = 0; mt < 2; mt++){
            #pragma unroll
            for (int s = 0; s < 2; s++){
                int rl = m0w + mt*16 + gid + s*8;
                float bv = bias[co0 + rl];
                float* orow = out + ((size_t)bb*C + co0 + rl)*HW + hw0;
                #pragma unroll
                for (int nt = 0; nt < 8; nt++){
                    int cs = n0w + nt*8 + tig*2;
                    float2 v = {c[mt][nt][s*2+0] + bv, c[mt][nt][s*2+1] + bv};
                    *(float2*)&orow[cs] = v;
                }
            }
        }
    } else {
        // modes 2,3: bias (+residual for 2), stage to smem, transposed write
        __syncthreads();   // done with A/B smem
        #pragma unroll
        for (int mt = 0; mt < 2; mt++){
            #pragma unroll
            for (int s = 0; s < 2; s++){
                int rl = m0w + mt*16 + gid + s*8;
                float bv;
                if (MODE == 3){
                    int co = co0 + rl;
                    bv = (co < 192) ? qb[co] : (co < 384 ? 0.0f : vb[co - 384]);
                } else {
                    bv = bias[co0 + rl];
                }
                const float* rrow = (MODE == 2)
                    ? (res + ((size_t)bz*C + co0 + rl)*HW + p0) : nullptr;
                #pragma unroll
                for (int nt = 0; nt < 8; nt++){
                    int cs = n0w + nt*8 + tig*2;
                    float v0 = c[mt][nt][s*2+0] + bv;
                    float v1 = c[mt][nt][s*2+1] + bv;
                    if (MODE == 2){
                        float2 rv = *(const float2*)&rrow[cs];
                        v0 += rv.x; v1 += rv.y;
                    }
                    stg[rl*260 + cs]     = v0;
                    stg[rl*260 + cs + 1] = v1;
                }
            }
        }
        __syncthreads();
        const int ldo = (MODE == 3) ? 576 : 192;
        const size_t pbase = (MODE == 3) ? (size_t)p0 : ((size_t)bz*HW + p0);
        #pragma unroll
        for (int r = 0; r < 4; r++){
            int pl = (t >> 2) + r*64;
            int cq = (t & 3) * 16;
            float vals[16];
            #pragma unroll
            for (int j = 0; j < 16; j++) vals[j] = stg[(cq + j)*260 + pl];
            float* op = out + (pbase + pl)*ldo + co0 + cq;
            *(float4*)&op[0]  = *(float4*)&vals[0];
            *(float4*)&op[4]  = *(float4*)&vals[4];
            *(float4*)&op[8]  = *(float4*)&vals[8];
            *(float4*)&op[12] = *(float4*)&vals[12];
        }
    }
}

// ---------------- fused depthwise 5x5 + 5x5 dil3 ----------------------------
__global__ void __launch_bounds__(256)
k_dwf(const float* __restrict__ in, const float* __restrict__ w1,
      const float* __restrict__ b1, const float* __restrict__ w2,
      const float* __restrict__ b2, float* __restrict__ out)
{
    __shared__ float s0[48][49];
    __shared__ float s1[44][45];
    __shared__ float wts[52];
    const int plane = blockIdx.y;
    const int c = plane % C;
    const int tile = blockIdx.x;
    const int y0 = (tile >> 2) * 32, x0 = (tile & 3) * 32;
    const int t = threadIdx.x;

    if (t < 25) wts[t] = w1[c*25 + t];
    else if (t < 50) wts[t] = w2[c*25 + t - 25];
    else if (t == 50) wts[50] = b1[c];
    else if (t == 51) wts[51] = b2[c];

    const float* ip = in + ((size_t)plane << 14);
    for (int idx = t; idx < 48*48; idx += 256){
        int yy = idx / 48, xx = idx - yy*48;
        int gy = y0 - 8 + yy, gx = x0 - 8 + xx;
        s0[yy][xx] = ((unsigned)gy < 128u && (unsigned)gx < 128u) ? ip[gy*128+gx] : 0.0f;
    }
    __syncthreads();

    for (int idx = t; idx < 44*44; idx += 256){
        int r = idx / 44, cc = idx - r*44;
        int gy = y0 - 6 + r, gx = x0 - 6 + cc;
        float v = 0.0f;
        if ((unsigned)gy < 128u && (unsigned)gx < 128u){
            v = wts[50];
            #pragma unroll
            for (int i = 0; i < 5; i++)
                #pragma unroll
                for (int j = 0; j < 5; j++)
                    v = fmaf(wts[i*5+j], s0[r+i][cc+j], v);
        }
        s1[r][cc] = v;
    }
    __syncthreads();

    for (int idx = t; idx < 1024; idx += 256){
        int r = idx >> 5, cc = idx & 31;
        float v = wts[51];
        #pragma unroll
        for (int i = 0; i < 5; i++)
            #pragma unroll
            for (int j = 0; j < 5; j++)
                v = fmaf(wts[25+i*5+j], s1[r+3*i][cc+3*j], v);
        out[((size_t)plane << 14) + (y0+r)*128 + x0 + cc] = v;
    }
}

// ---------------- LayerNorm over C per pixel (BHWC) -------------------------
__global__ void k_ln(const float* __restrict__ in, const float* __restrict__ g,
                     const float* __restrict__ bta, float* __restrict__ out)
{
    int gw = (blockIdx.x*blockDim.x + threadIdx.x) >> 5;
    int lane = threadIdx.x & 31;
    if (gw >= NPIX) return;
    const float* r = in + (size_t)gw*192;
    float v[6]; float s = 0.0f;
    #pragma unroll
    for (int t = 0; t < 6; t++){ v[t] = r[lane + 32*t]; s += v[t]; }
    #pragma unroll
    for (int o = 16; o > 0; o >>= 1) s += __shfl_xor_sync(0xffffffffu, s, o);
    float mu = s * (1.0f/192.0f);
    float q = 0.0f;
    #pragma unroll
    for (int t = 0; t < 6; t++){ float d = v[t]-mu; q += d*d; }
    #pragma unroll
    for (int o = 16; o > 0; o >>= 1) q += __shfl_xor_sync(0xffffffffu, q, o);
    float inv = rsqrtf(q * (1.0f/192.0f) + 1e-5f);
    float* w = out + (size_t)gw*192;
    #pragma unroll
    for (int t = 0; t < 6; t++){
        int c = lane + 32*t;
        w[c] = (v[t]-mu)*inv*g[c] + bta[c];
    }
}

// ---------------- SwinV2 cosine window attention ----------------------------
__global__ void k_attn(const float* __restrict__ qkv, const float* __restrict__ tbl,
                       const float* __restrict__ lsc, float* __restrict__ out)
{
    extern __shared__ float sm[];
    float* kn = sm;
    float* vv = sm + 8192;
    float* sb = sm + 16384;
    const int w = blockIdx.x, h = blockIdx.y, i = threadIdx.x;
    const int b = w >> 6, wy = (w >> 3) & 7, wx = w & 7;
    const int iy = i >> 4, ix = i & 15;
    const size_t p_i = (size_t)b*HW + (size_t)(wy*16+iy)*128 + (wx*16+ix);

    {
        const float4* kr = (const float4*)(qkv + p_i*576 + 192 + h*32);
        const float4* vr = (const float4*)(qkv + p_i*576 + 384 + h*32);
        float4 kt[8]; float ss = 0.0f;
        #pragma unroll
        for (int d = 0; d < 8; d++){
            kt[d] = kr[d];
            ss += kt[d].x*kt[d].x + kt[d].y*kt[d].y + kt[d].z*kt[d].z + kt[d].w*kt[d].w;
        }
        float inv = 1.0f / fmaxf(sqrtf(ss), 1e-12f);
        float4* kd = (float4*)(kn + i*32);
        float4* vd = (float4*)(vv + i*32);
        #pragma unroll
        for (int d = 0; d < 8; d++){
            float4 tt = kt[d]; tt.x*=inv; tt.y*=inv; tt.z*=inv; tt.w*=inv;
            kd[d] = tt;
            vd[d] = vr[d];
        }
    }
    for (int t = i; t < 961; t += 256) sb[t] = tbl[t*6 + h];

    float4 q[8];
    {
        const float4* qr = (const float4*)(qkv + p_i*576 + h*32);
        float ss = 0.0f;
        #pragma unroll
        for (int d = 0; d < 8; d++){
            q[d] = qr[d];
            ss += q[d].x*q[d].x + q[d].y*q[d].y + q[d].z*q[d].z + q[d].w*q[d].w;
        }
        float inv = 1.0f / fmaxf(sqrtf(ss), 1e-12f);
        #pragma unroll
        for (int d = 0; d < 8; d++){ q[d].x*=inv; q[d].y*=inv; q[d].z*=inv; q[d].w*=inv; }
    }
    const float scale = __expf(fminf(lsc[h], 4.6051702f));
    __syncthreads();

    float m = -1e30f, l = 0.0f;
    float4 o[8] = {};
    for (int c0 = 0; c0 < 256; c0 += 32){
        float s[32]; float cm = -1e30f;
        #pragma unroll
        for (int j = 0; j < 32; j++){
            const float4* kr = (const float4*)(kn + (c0+j)*32);
            float dot = 0.0f;
            #pragma unroll
            for (int d = 0; d < 8; d++){
                float4 kk = kr[d];
                dot += q[d].x*kk.x + q[d].y*kk.y + q[d].z*kk.z + q[d].w*kk.w;
            }
            int mm = c0 + j, my = mm >> 4, mx = mm & 15;
            float bias = sb[(iy-my+15)*31 + (ix-mx+15)];
            s[j] = fmaf(scale, dot, bias);
            cm = fmaxf(cm, s[j]);
        }
        float nm = fmaxf(m, cm);
        float corr = fexp(m - nm);
        l *= corr;
        #pragma unroll
        for (int d = 0; d < 8; d++){ o[d].x*=corr; o[d].y*=corr; o[d].z*=corr; o[d].w*=corr; }
        #pragma unroll
        for (int j = 0; j < 32; j++){
            float p = fexp(s[j] - nm);
            l += p;
            const float4* vr = (const float4*)(vv + (c0+j)*32);
            #pragma unroll
            for (int d = 0; d < 8; d++){
                float4 vk = vr[d];
                o[d].x = fmaf(p, vk.x, o[d].x);
                o[d].y = fmaf(p, vk.y, o[d].y);
                o[d].z = fmaf(p, vk.z, o[d].z);
                o[d].w = fmaf(p, vk.w, o[d].w);
            }
        }
        m = nm;
    }
    float inv = 1.0f / l;
    float4* op = (float4*)(out + p_i*192 + h*32);
    #pragma unroll
    for (int d = 0; d < 8; d++){
        float4 tt = o[d]; tt.x*=inv; tt.y*=inv; tt.z*=inv; tt.w*=inv;
        op[d] = tt;
    }
}

// ---------------------------------------------------------------------------
extern "C" void kernel_launch(void* const* d_in, const int* in_sizes, int n_in,
                              void* d_out, int out_size)
{
    const float* x      = (const float*)d_in[0];
    const float* p1_w   = (const float*)d_in[1];
    const float* p1_b   = (const float*)d_in[2];
    const float* pw_w   = (const float*)d_in[3];
    const float* pw_b   = (const float*)d_in[4];
    const float* dw_w   = (const float*)d_in[5];
    const float* dw_b   = (const float*)d_in[6];
    const float* dd_w   = (const float*)d_in[7];
    const float* dd_b   = (const float*)d_in[8];
    const float* p2_w   = (const float*)d_in[9];
    const float* p2_b   = (const float*)d_in[10];
    const float* ln_g   = (const float*)d_in[11];
    const float* ln_b   = (const float*)d_in[12];
    const float* qkv_w  = (const float*)d_in[13];
    const float* q_bias = (const float*)d_in[14];
    const float* v_bias = (const float*)d_in[15];
    const float* lsc    = (const float*)d_in[16];
    const float* cpb_w1 = (const float*)d_in[17];
    const float* cpb_b1 = (const float*)d_in[18];
    const float* cpb_w2 = (const float*)d_in[19];
    const float* proj_w = (const float*)d_in[20];
    const float* proj_b = (const float*)d_in[21];
    float* outp = (float*)d_out;

    float *gy, *ga, *gb, *gq, *gt;
    cudaGetSymbolAddress((void**)&gy, g_y);
    cudaGetSymbolAddress((void**)&ga, g_a);
    cudaGetSymbolAddress((void**)&gb, g_b);
    cudaGetSymbolAddress((void**)&gq, g_qkv);
    cudaGetSymbolAddress((void**)&gt, g_tbl);

    const int ATTN_SMEM = (8192 + 8192 + 961) * 4;
    cudaFuncSetAttribute(k_attn, cudaFuncAttributeMaxDynamicSharedMemorySize, ATTN_SMEM);
    const int GEMM_SMEM_LOAD  = (64*20*2 + 16*260*2) * 4;   // 43520
    const int GEMM_SMEM_STAGE = 64*260*4;                   // 66560
    cudaFuncSetAttribute(k_gemm<2>, cudaFuncAttributeMaxDynamicSharedMemorySize, GEMM_SMEM_STAGE);
    cudaFuncSetAttribute(k_gemm<3>, cudaFuncAttributeMaxDynamicSharedMemorySize, GEMM_SMEM_STAGE);

    dim3 gNCHW(HW/256, 3, BATCH);   // 64,3,4

    // CPB bias table (independent)
    k_cpb<<<961, 128>>>(cpb_w1, cpb_b1, cpb_w2, gt);

    // VAB conv block
    k_gemm<0><<<gNCHW, 256, GEMM_SMEM_LOAD>>>(x,  p1_w, p1_b, nullptr, nullptr, nullptr, nullptr, gy);
    k_gemm<1><<<gNCHW, 256, GEMM_SMEM_LOAD>>>(gy, pw_w, pw_b, nullptr, nullptr, nullptr, nullptr, ga);
    k_dwf<<<dim3(16, BATCH*C), 256>>>(ga, dw_w, dw_b, dd_w, dd_b, gb);
    k_gemm<2><<<gNCHW, 256, GEMM_SMEM_STAGE>>>(gy, p2_w, p2_b, gb, x, nullptr, nullptr, ga);

    // LayerNorm (BHWC)
    k_ln<<<NPIX/8, 256>>>(ga, ln_g, ln_b, gy);

    // QKV projection: [p][192] -> [p][576]
    k_gemm<3><<<dim3(NPIX/256, 9), 256, GEMM_SMEM_STAGE>>>(gy, qkv_w, nullptr, nullptr, nullptr, q_bias, v_bias, gq);

    // Windowed cosine attention -> BHWC in ga
    k_attn<<<dim3(NWIN, NH), 256, ATTN_SMEM>>>(gq, gt, lsc, ga);

    // Output projection -> NCHW d_out
    k_gemm<4><<<dim3(NPIX/256, 3), 256, GEMM_SMEM_LOAD>>>(ga, proj_w, proj_b, nullptr, nullptr, nullptr, nullptr, outp);
}

// round 4
// speedup vs baseline: 2.1633x; 1.3572x over previous
#include <cuda_runtime.h>
#include <cuda_bf16.h>
#include <math.h>

#define BATCH 4
#define C 192
#define HW 16384            // 128*128
#define NPIX (BATCH*HW)     // 65536
#define NH 6
#define HD 32
#define NWIN 256
#define NTOK 256

// ---------------- scratch (device globals; no allocations allowed) ----------
__device__ float g_y[BATCH*C*HW];
__device__ float g_a[BATCH*C*HW];
__device__ float g_b[BATCH*C*HW];
__device__ float g_qkv[(size_t)NPIX*576];
__device__ float g_tbl[961*NH];
__device__ float g_bias[NH*256*256];       // expanded CPB bias per head

// ---------------- fast exp on the FMA pipe ---------------------------------
__device__ __forceinline__ float fexp(float x){
    float z  = fmaxf(x * 1.44269504088896f, -126.0f);
    float mz = z + 12582912.0f;
    int   iz = __float_as_int(mz);
    float zi = mz - 12582912.0f;
    float f  = z - zi;
    float p  = 1.0f + f*(0.6931471806f + f*(0.2402265070f + f*(0.0555041087f
              + f*(0.0096181291f + f*0.0013333558f))));
    return __int_as_float(__float_as_int(p) + (iz << 23));
}

// ---------------- bf16 split helpers ---------------------------------------
__device__ __forceinline__ unsigned packbf(float lo, float hi){
    unsigned r;
    asm("cvt.rn.bf16x2.f32 %0, %1, %2;" : "=r"(r) : "f"(hi), "f"(lo));
    return r;
}
__device__ __forceinline__ float bflo(unsigned u){ return __uint_as_float(u << 16); }
__device__ __forceinline__ float bfhi(unsigned u){ return __uint_as_float(u & 0xffff0000u); }

__device__ __forceinline__ void split2(float a, float b, unsigned& h, unsigned& l){
    h = packbf(a, b);
    l = packbf(a - bflo(h), b - bfhi(h));
}

__device__ __forceinline__ void mma_bf16(float c[4], const unsigned a[4],
                                         unsigned b0, unsigned b1){
    asm("mma.sync.aligned.m16n8k16.row.col.f32.bf16.bf16.f32 "
        "{%0,%1,%2,%3},{%4,%5,%6,%7},{%8,%9},{%0,%1,%2,%3};"
        : "+f"(c[0]), "+f"(c[1]), "+f"(c[2]), "+f"(c[3])
        : "r"(a[0]), "r"(a[1]), "r"(a[2]), "r"(a[3]), "r"(b0), "r"(b1));
}

// ---------------- CPB MLP table --------------------------------------------
__global__ void k_cpb(const float* __restrict__ w1, const float* __restrict__ b1,
                      const float* __restrict__ w2, float* __restrict__ tbl)
{
    int r = blockIdx.x;
    int t = threadIdx.x;
    float dy = (float)(r / 31) - 15.0f;
    float dx = (float)(r % 31) - 15.0f;
    float u0 = dy / 15.0f * 8.0f, u1 = dx / 15.0f * 8.0f;
    float t0 = copysignf(log2f(fabsf(u0) + 1.0f) * (1.0f/3.0f), u0);
    float t1 = copysignf(log2f(fabsf(u1) + 1.0f) * (1.0f/3.0f), u1);
    float acc[6] = {0,0,0,0,0,0};
    for (int u = t; u < 512; u += 128){
        float hv = fmaxf(w1[2*u]*t0 + w1[2*u+1]*t1 + b1[u], 0.0f);
        #pragma unroll
        for (int h = 0; h < 6; h++) acc[h] += hv * w2[h*512 + u];
    }
    __shared__ float red[6][128];
    #pragma unroll
    for (int h = 0; h < 6; h++) red[h][t] = acc[h];
    __syncthreads();
    for (int off = 64; off > 0; off >>= 1){
        if (t < off){
            #pragma unroll
            for (int h = 0; h < 6; h++) red[h][t] += red[h][t+off];
        }
        __syncthreads();
    }
    if (t < 6){
        float v = red[t][0];
        tbl[r*6 + t] = 16.0f / (1.0f + expf(-v));
    }
}

// ---------------- expand CPB bias to [h][256][256] --------------------------
__global__ void k_bias(const float* __restrict__ tbl, float* __restrict__ bg)
{
    int r = blockIdx.x, h = blockIdx.y, c = threadIdx.x;
    int iy = r >> 4, ix = r & 15, my = c >> 4, mx = c & 15;
    int idx = (iy - my + 15)*31 + (ix - mx + 15);
    bg[((size_t)h*256 + r)*256 + c] = tbl[idx*6 + h];
}

// ---------------- tensor-core GEMM (bf16 hi/lo split, fp32 accum) ----------
// MODE 0: p1; 1: pw; 2: p2 (gate+res->BHWC); 3: qkv; 4: proj->NCHW
template<int MODE>
__global__ void __launch_bounds__(256, 2)
k_gemm(const float* __restrict__ X, const float* __restrict__ W,
       const float* __restrict__ bias, const float* __restrict__ X2,
       const float* __restrict__ res, const float* __restrict__ qb,
       const float* __restrict__ vb, float* __restrict__ out)
{
    extern __shared__ unsigned smem_u[];
    unsigned* Ah = smem_u;                  // 64*20
    unsigned* Al = Ah + 64*20;
    unsigned* Bh = Al + 64*20;              // 16*260
    unsigned* Bl = Bh + 16*260;
    float* stg = (float*)smem_u;            // overlay (modes 2,3)

    const int t = threadIdx.x;
    const int wid = t >> 5, lane = t & 31;
    const int gid = lane >> 2, tig = lane & 3;
    const int m0w = (wid & 1) * 32;
    const int n0w = (wid >> 1) * 64;

    const int p0  = blockIdx.x * 256;
    const int co0 = blockIdx.y * 64;
    const int bz  = (MODE <= 2) ? blockIdx.z : 0;

    const float* Xb  = (MODE <= 2) ? (X + (size_t)bz*C*HW) : X;
    const float* X2b = (MODE == 2) ? (X2 + (size_t)bz*C*HW) : nullptr;

    float c[2][8][4];
    #pragma unroll
    for (int i = 0; i < 2; i++)
        #pragma unroll
        for (int j = 0; j < 8; j++)
            #pragma unroll
            for (int q = 0; q < 4; q++) c[i][j][q] = 0.0f;

    const int ar  = t >> 2;
    const int akq = (t & 3) * 8;

    for (int kc = 0; kc < 6; kc++){
        const int k0 = kc * 32;
        __syncthreads();
        {
            const float* wp = &W[(size_t)(co0 + ar)*192 + k0 + akq];
            float4 w0 = *(const float4*)wp;
            float4 w1 = *(const float4*)(wp + 4);
            uint4 h, l;
            split2(w0.x, w0.y, h.x, l.x);
            split2(w0.z, w0.w, h.y, l.y);
            split2(w1.x, w1.y, h.z, l.z);
            split2(w1.z, w1.w, h.w, l.w);
            *(uint4*)&Ah[ar*20 + akq/2] = h;
            *(uint4*)&Al[ar*20 + akq/2] = l;
        }
        if (MODE <= 2){
            const int bp  = (t & 63) * 4;
            const int bk2 = t >> 6;
            #pragma unroll
            for (int r = 0; r < 4; r++){
                int k2i = bk2 + r*4;
                int k = k0 + k2i*2;
                const float* xr = Xb + (size_t)k*HW + p0 + bp;
                float4 e = *(const float4*)xr;
                float4 o = *(const float4*)(xr + HW);
                if (MODE == 2){
                    const float* mr = X2b + (size_t)k*HW + p0 + bp;
                    float4 m1 = *(const float4*)mr;
                    float4 m2 = *(const float4*)(mr + HW);
                    e.x*=m1.x; e.y*=m1.y; e.z*=m1.z; e.w*=m1.w;
                    o.x*=m2.x; o.y*=m2.y; o.z*=m2.z; o.w*=m2.w;
                }
                uint4 h, l;
                split2(e.x, o.x, h.x, l.x);
                split2(e.y, o.y, h.y, l.y);
                split2(e.z, o.z, h.z, l.z);
                split2(e.w, o.w, h.w, l.w);
                *(uint4*)&Bh[k2i*260 + bp] = h;
                *(uint4*)&Bl[k2i*260 + bp] = l;
            }
        } else {
            const int fi = t & 7;
            const int k = k0 + fi*4;
            #pragma unroll
            for (int r = 0; r < 8; r++){
                int pl = (t >> 3) + r*32;
                float4 v = *(const float4*)&Xb[(size_t)(p0 + pl)*192 + k];
                unsigned h0, l0, h1, l1;
                split2(v.x, v.y, h0, l0);
                split2(v.z, v.w, h1, l1);
                Bh[(fi*2  )*260 + pl] = h0;
                Bh[(fi*2+1)*260 + pl] = h1;
                Bl[(fi*2  )*260 + pl] = l0;
                Bl[(fi*2+1)*260 + pl] = l1;
            }
        }
        __syncthreads();

        #pragma unroll
        for (int ks = 0; ks < 2; ks++){
            const int kb = ks * 8;
            unsigned ah[2][4], al2[2][4];
            #pragma unroll
            for (int mt = 0; mt < 2; mt++){
                int mr = m0w + mt*16 + gid;
                ah[mt][0]  = Ah[mr*20 + kb + tig];
                ah[mt][1]  = Ah[(mr+8)*20 + kb + tig];
                ah[mt][2]  = Ah[mr*20 + kb + tig + 4];
                ah[mt][3]  = Ah[(mr+8)*20 + kb + tig + 4];
                al2[mt][0] = Al[mr*20 + kb + tig];
                al2[mt][1] = Al[(mr+8)*20 + kb + tig];
                al2[mt][2] = Al[mr*20 + kb + tig + 4];
                al2[mt][3] = Al[(mr+8)*20 + kb + tig + 4];
            }
            #pragma unroll
            for (int nt = 0; nt < 8; nt++){
                int nn = n0w + nt*8 + gid;
                unsigned bh0 = Bh[(kb+tig  )*260 + nn];
                unsigned bh1 = Bh[(kb+tig+4)*260 + nn];
                unsigned bl0 = Bl[(kb+tig  )*260 + nn];
                unsigned bl1 = Bl[(kb+tig+4)*260 + nn];
                #pragma unroll
                for (int mt = 0; mt < 2; mt++){
                    mma_bf16(c[mt][nt], ah[mt],  bh0, bh1);
                    mma_bf16(c[mt][nt], ah[mt],  bl0, bl1);
                    mma_bf16(c[mt][nt], al2[mt], bh0, bh1);
                }
            }
        }
    }

    if (MODE == 0 || MODE == 1){
        #pragma unroll
        for (int mt = 0; mt < 2; mt++){
            #pragma unroll
            for (int s = 0; s < 2; s++){
                int rl = m0w + mt*16 + gid + s*8;
                float bv = bias[co0 + rl];
                float* orow = out + ((size_t)bz*C + co0 + rl)*HW + p0;
                #pragma unroll
                for (int nt = 0; nt < 8; nt++){
                    int cs = n0w + nt*8 + tig*2;
                    float v0 = c[mt][nt][s*2+0] + bv;
                    float v1 = c[mt][nt][s*2+1] + bv;
                    if (MODE == 0){
                        v0 = 0.5f*v0*(1.0f + erff(v0*0.70710678f));
                        v1 = 0.5f*v1*(1.0f + erff(v1*0.70710678f));
                    }
                    float2 v = {v0, v1};
                    *(float2*)&orow[cs] = v;
                }
            }
        }
    } else if (MODE == 4){
        const int bb = p0 >> 14;
        const int hw0 = p0 & 16383;
        #pragma unroll
        for (int mt = 0; mt < 2; mt++){
            #pragma unroll
            for (int s = 0; s < 2; s++){
                int rl = m0w + mt*16 + gid + s*8;
                float bv = bias[co0 + rl];
                float* orow = out + ((size_t)bb*C + co0 + rl)*HW + hw0;
                #pragma unroll
                for (int nt = 0; nt < 8; nt++){
                    int cs = n0w + nt*8 + tig*2;
                    float2 v = {c[mt][nt][s*2+0] + bv, c[mt][nt][s*2+1] + bv};
                    *(float2*)&orow[cs] = v;
                }
            }
        }
    } else {
        __syncthreads();
        #pragma unroll
        for (int mt = 0; mt < 2; mt++){
            #pragma unroll
            for (int s = 0; s < 2; s++){
                int rl = m0w + mt*16 + gid + s*8;
                float bv;
                if (MODE == 3){
                    int co = co0 + rl;
                    bv = (co < 192) ? qb[co] : (co < 384 ? 0.0f : vb[co - 384]);
                } else {
                    bv = bias[co0 + rl];
                }
                const float* rrow = (MODE == 2)
                    ? (res + ((size_t)bz*C + co0 + rl)*HW + p0) : nullptr;
                #pragma unroll
                for (int nt = 0; nt < 8; nt++){
                    int cs = n0w + nt*8 + tig*2;
                    float v0 = c[mt][nt][s*2+0] + bv;
                    float v1 = c[mt][nt][s*2+1] + bv;
                    if (MODE == 2){
                        float2 rv = *(const float2*)&rrow[cs];
                        v0 += rv.x; v1 += rv.y;
                    }
                    stg[rl*260 + cs]     = v0;
                    stg[rl*260 + cs + 1] = v1;
                }
            }
        }
        __syncthreads();
        const int ldo = (MODE == 3) ? 576 : 192;
        const size_t pbase = (MODE == 3) ? (size_t)p0 : ((size_t)bz*HW + p0);
        #pragma unroll
        for (int r = 0; r < 4; r++){
            int pl = (t >> 2) + r*64;
            int cq = (t & 3) * 16;
            float vals[16];
            #pragma unroll
            for (int j = 0; j < 16; j++) vals[j] = stg[(cq + j)*260 + pl];
            float* op = out + (pbase + pl)*ldo + co0 + cq;
            *(float4*)&op[0]  = *(float4*)&vals[0];
            *(float4*)&op[4]  = *(float4*)&vals[4];
            *(float4*)&op[8]  = *(float4*)&vals[8];
            *(float4*)&op[12] = *(float4*)&vals[12];
        }
    }
}

// ---------------- fused depthwise 5x5 + 5x5 dil3 ----------------------------
__global__ void __launch_bounds__(256)
k_dwf(const float* __restrict__ in, const float* __restrict__ w1,
      const float* __restrict__ b1, const float* __restrict__ w2,
      const float* __restrict__ b2, float* __restrict__ out)
{
    __shared__ float s0[48][49];
    __shared__ float s1[44][45];
    __shared__ float wts[52];
    const int plane = blockIdx.y;
    const int c = plane % C;
    const int tile = blockIdx.x;
    const int y0 = (tile >> 2) * 32, x0 = (tile & 3) * 32;
    const int t = threadIdx.x;

    if (t < 25) wts[t] = w1[c*25 + t];
    else if (t < 50) wts[t] = w2[c*25 + t - 25];
    else if (t == 50) wts[50] = b1[c];
    else if (t == 51) wts[51] = b2[c];

    const float* ip = in + ((size_t)plane << 14);
    for (int idx = t; idx < 48*48; idx += 256){
        int yy = idx / 48, xx = idx - yy*48;
        int gy = y0 - 8 + yy, gx = x0 - 8 + xx;
        s0[yy][xx] = ((unsigned)gy < 128u && (unsigned)gx < 128u) ? ip[gy*128+gx] : 0.0f;
    }
    __syncthreads();

    for (int idx = t; idx < 44*44; idx += 256){
        int r = idx / 44, cc = idx - r*44;
        int gy = y0 - 6 + r, gx = x0 - 6 + cc;
        float v = 0.0f;
        if ((unsigned)gy < 128u && (unsigned)gx < 128u){
            v = wts[50];
            #pragma unroll
            for (int i = 0; i < 5; i++)
                #pragma unroll
                for (int j = 0; j < 5; j++)
                    v = fmaf(wts[i*5+j], s0[r+i][cc+j], v);
        }
        s1[r][cc] = v;
    }
    __syncthreads();

    for (int idx = t; idx < 1024; idx += 256){
        int r = idx >> 5, cc = idx & 31;
        float v = wts[51];
        #pragma unroll
        for (int i = 0; i < 5; i++)
            #pragma unroll
            for (int j = 0; j < 5; j++)
                v = fmaf(wts[25+i*5+j], s1[r+3*i][cc+3*j], v);
        out[((size_t)plane << 14) + (y0+r)*128 + x0 + cc] = v;
    }
}

// ---------------- LayerNorm over C per pixel (BHWC) -------------------------
__global__ void k_ln(const float* __restrict__ in, const float* __restrict__ g,
                     const float* __restrict__ bta, float* __restrict__ out)
{
    int gw = (blockIdx.x*blockDim.x + threadIdx.x) >> 5;
    int lane = threadIdx.x & 31;
    if (gw >= NPIX) return;
    const float* r = in + (size_t)gw*192;
    float v[6]; float s = 0.0f;
    #pragma unroll
    for (int t = 0; t < 6; t++){ v[t] = r[lane + 32*t]; s += v[t]; }
    #pragma unroll
    for (int o = 16; o > 0; o >>= 1) s += __shfl_xor_sync(0xffffffffu, s, o);
    float mu = s * (1.0f/192.0f);
    float q = 0.0f;
    #pragma unroll
    for (int t = 0; t < 6; t++){ float d = v[t]-mu; q += d*d; }
    #pragma unroll
    for (int o = 16; o > 0; o >>= 1) q += __shfl_xor_sync(0xffffffffu, q, o);
    float inv = rsqrtf(q * (1.0f/192.0f) + 1e-5f);
    float* w = out + (size_t)gw*192;
    #pragma unroll
    for (int t = 0; t < 6; t++){
        int c = lane + 32*t;
        w[c] = (v[t]-mu)*inv*g[c] + bta[c];
    }
}

// ---------------- SwinV2 cosine window attention (tensor-core flash) --------
// grid (window, head), 256 threads = 8 warps; warp w owns query rows 32w..32w+31
__global__ void __launch_bounds__(256, 1)
k_attn(const float* __restrict__ qkv, const float* __restrict__ bgl,
       const float* __restrict__ lsc, float* __restrict__ out)
{
    extern __shared__ unsigned sm[];
    unsigned* Kh = sm;                     // [16][264]
    unsigned* Kl = Kh + 16*264;
    unsigned* Vh = Kl + 16*264;            // [128][40]
    unsigned* Vl = Vh + 128*40;
    float* qs = (float*)(Vl + 128*40);     // [256]

    const int w = blockIdx.x, h = blockIdx.y, t = threadIdx.x;
    const int b = w >> 6, wy = (w >> 3) & 7, wx = w & 7;
    const int wid = t >> 5, lane = t & 31, gid = lane >> 2, tig = lane & 3;
    const float scale = __expf(fminf(lsc[h], 4.6051702f));
    const size_t pixbase = (size_t)b*HW + (size_t)(wy*16)*128 + wx*16;

    // ---- stage K (normalized, packed over feature dim) + q scales ----
    {
        const int tok = t;
        const size_t pp = pixbase + (size_t)(tok >> 4)*128 + (tok & 15);
        const float* qr = qkv + pp*576 + h*32;
        const float* kr = qr + 192;
        float kv[32]; float ssq = 0.0f, ssk = 0.0f;
        #pragma unroll
        for (int d = 0; d < 8; d++){
            float4 q4 = ((const float4*)qr)[d];
            ssq += q4.x*q4.x + q4.y*q4.y + q4.z*q4.z + q4.w*q4.w;
            float4 k4 = ((const float4*)kr)[d];
            kv[4*d]=k4.x; kv[4*d+1]=k4.y; kv[4*d+2]=k4.z; kv[4*d+3]=k4.w;
            ssk += k4.x*k4.x + k4.y*k4.y + k4.z*k4.z + k4.w*k4.w;
        }
        qs[tok] = scale / fmaxf(sqrtf(ssq), 1e-12f);
        float ki = 1.0f / fmaxf(sqrtf(ssk), 1e-12f);
        #pragma unroll
        for (int d2 = 0; d2 < 16; d2++){
            unsigned hh, ll;
            split2(kv[2*d2]*ki, kv[2*d2+1]*ki, hh, ll);
            Kh[d2*264 + tok] = hh;
            Kl[d2*264 + tok] = ll;
        }
    }
    // ---- stage V (packed over token pairs) ----
    {
        const int t2 = t >> 1, dh = (t & 1) * 16;
        const size_t pa = pixbase + (size_t)((2*t2) >> 4)*128 + ((2*t2) & 15);
        const size_t pb = pixbase + (size_t)((2*t2+1) >> 4)*128 + ((2*t2+1) & 15);
        const float* v0 = qkv + pa*576 + 384 + h*32 + dh;
        const float* v1 = qkv + pb*576 + 384 + h*32 + dh;
        #pragma unroll
        for (int dq = 0; dq < 4; dq++){
            float4 a = ((const float4*)v0)[dq];
            float4 bb = ((const float4*)v1)[dq];
            unsigned hh, ll;
            split2(a.x, bb.x, hh, ll); Vh[t2*40+dh+4*dq+0]=hh; Vl[t2*40+dh+4*dq+0]=ll;
            split2(a.y, bb.y, hh, ll); Vh[t2*40+dh+4*dq+1]=hh; Vl[t2*40+dh+4*dq+1]=ll;
            split2(a.z, bb.z, hh, ll); Vh[t2*40+dh+4*dq+2]=hh; Vl[t2*40+dh+4*dq+2]=ll;
            split2(a.w, bb.w, hh, ll); Vh[t2*40+dh+4*dq+3]=hh; Vl[t2*40+dh+4*dq+3]=ll;
        }
    }
    __syncthreads();

    // ---- Q A-fragments (scaled + normalized, hi/lo split) ----
    unsigned qh[2][2][4], ql[2][2][4];
    #pragma unroll
    for (int mt = 0; mt < 2; mt++){
        int r1 = wid*32 + mt*16 + gid, r2 = r1 + 8;
        float s1 = qs[r1], s2 = qs[r2];
        const float* q1 = qkv + (pixbase + (size_t)(r1>>4)*128 + (r1&15))*576 + h*32;
        const float* q2 = qkv + (pixbase + (size_t)(r2>>4)*128 + (r2&15))*576 + h*32;
        #pragma unroll
        for (int ks = 0; ks < 2; ks++){
            float2 e1 = *(const float2*)(q1 + 16*ks + 2*tig);
            float2 e2 = *(const float2*)(q2 + 16*ks + 2*tig);
            float2 f1 = *(const float2*)(q1 + 16*ks + 8 + 2*tig);
            float2 f2 = *(const float2*)(q2 + 16*ks + 8 + 2*tig);
            split2(e1.x*s1, e1.y*s1, qh[mt][ks][0], ql[mt][ks][0]);
            split2(e2.x*s2, e2.y*s2, qh[mt][ks][1], ql[mt][ks][1]);
            split2(f1.x*s1, f1.y*s1, qh[mt][ks][2], ql[mt][ks][2]);
            split2(f2.x*s2, f2.y*s2, qh[mt][ks][3], ql[mt][ks][3]);
        }
    }

    float m[4] = {-1e30f,-1e30f,-1e30f,-1e30f};
    float l[4] = {0,0,0,0};
    float o[2][4][4];
    #pragma unroll
    for (int i=0;i<2;i++) for (int j=0;j<4;j++) for (int q=0;q<4;q++) o[i][j][q]=0.0f;

    const float* bg = bgl + (size_t)h*256*256;

    for (int ch = 0; ch < 4; ch++){
        const int c0 = ch * 64;
        float c[2][8][4];
        #pragma unroll
        for (int i=0;i<2;i++) for (int j=0;j<8;j++) for (int q=0;q<4;q++) c[i][j][q]=0.0f;

        // S = Qn·Kn^T (3-way hi/lo)
        #pragma unroll
        for (int ks = 0; ks < 2; ks++){
            #pragma unroll
            for (int nt = 0; nt < 8; nt++){
                int n = c0 + nt*8 + gid;
                unsigned bh0 = Kh[(8*ks+tig  )*264 + n];
                unsigned bh1 = Kh[(8*ks+tig+4)*264 + n];
                unsigned bl0 = Kl[(8*ks+tig  )*264 + n];
                unsigned bl1 = Kl[(8*ks+tig+4)*264 + n];
                #pragma unroll
                for (int mt = 0; mt < 2; mt++){
                    mma_bf16(c[mt][nt], qh[mt][ks], bh0, bh1);
                    mma_bf16(c[mt][nt], qh[mt][ks], bl0, bl1);
                    mma_bf16(c[mt][nt], ql[mt][ks], bh0, bh1);
                }
            }
        }

        // + bias, row max
        float cm[4] = {-1e30f,-1e30f,-1e30f,-1e30f};
        #pragma unroll
        for (int mt = 0; mt < 2; mt++){
            int r1 = wid*32 + mt*16 + gid, r2 = r1 + 8;
            #pragma unroll
            for (int nt = 0; nt < 8; nt++){
                int cc = c0 + nt*8 + 2*tig;
                float2 b1 = *(const float2*)&bg[(size_t)r1*256 + cc];
                float2 b2 = *(const float2*)&bg[(size_t)r2*256 + cc];
                c[mt][nt][0] += b1.x; c[mt][nt][1] += b1.y;
                c[mt][nt][2] += b2.x; c[mt][nt][3] += b2.y;
                cm[2*mt+0] = fmaxf(cm[2*mt+0], fmaxf(c[mt][nt][0], c[mt][nt][1]));
                cm[2*mt+1] = fmaxf(cm[2*mt+1], fmaxf(c[mt][nt][2], c[mt][nt][3]));
            }
        }
        #pragma unroll
        for (int q = 0; q < 4; q++){
            cm[q] = fmaxf(cm[q], __shfl_xor_sync(0xffffffffu, cm[q], 1));
            cm[q] = fmaxf(cm[q], __shfl_xor_sync(0xffffffffu, cm[q], 2));
        }
        float corr[4];
        #pragma unroll
        for (int q = 0; q < 4; q++){
            float nm = fmaxf(m[q], cm[q]);
            corr[q] = fexp(m[q] - nm);
            m[q] = nm;
            l[q] *= corr[q];
        }
        #pragma unroll
        for (int mt = 0; mt < 2; mt++)
            #pragma unroll
            for (int nt2 = 0; nt2 < 4; nt2++){
                o[mt][nt2][0] *= corr[2*mt];   o[mt][nt2][1] *= corr[2*mt];
                o[mt][nt2][2] *= corr[2*mt+1]; o[mt][nt2][3] *= corr[2*mt+1];
            }

        // P = exp(S-m); PV accumulate (3-way hi/lo)
        #pragma unroll
        for (int tt = 0; tt < 4; tt++){
            unsigned ph[2][4], pl[2][4];
            #pragma unroll
            for (int mt = 0; mt < 2; mt++){
                float p0 = fexp(c[mt][2*tt  ][0] - m[2*mt]);
                float p1 = fexp(c[mt][2*tt  ][1] - m[2*mt]);
                float p2 = fexp(c[mt][2*tt  ][2] - m[2*mt+1]);
                float p3 = fexp(c[mt][2*tt  ][3] - m[2*mt+1]);
                float p4 = fexp(c[mt][2*tt+1][0] - m[2*mt]);
                float p5 = fexp(c[mt][2*tt+1][1] - m[2*mt]);
                float p6 = fexp(c[mt][2*tt+1][2] - m[2*mt+1]);
                float p7 = fexp(c[mt][2*tt+1][3] - m[2*mt+1]);
                l[2*mt]   += p0 + p1 + p4 + p5;
                l[2*mt+1] += p2 + p3 + p6 + p7;
                split2(p0, p1, ph[mt][0], pl[mt][0]);
                split2(p2, p3, ph[mt][1], pl[mt][1]);
                split2(p4, p5, ph[mt][2], pl[mt][2]);
                split2(p6, p7, ph[mt][3], pl[mt][3]);
            }
            const int base = (c0 + 16*tt) >> 1;
            #pragma unroll
            for (int nt2 = 0; nt2 < 4; nt2++){
                int dcol = nt2*8 + gid;
                unsigned vh0 = Vh[(base+tig  )*40 + dcol];
                unsigned vh1 = Vh[(base+tig+4)*40 + dcol];
                unsigned vl0 = Vl[(base+tig  )*40 + dcol];
                unsigned vl1 = Vl[(base+tig+4)*40 + dcol];
                #pragma unroll
                for (int mt = 0; mt < 2; mt++){
                    mma_bf16(o[mt][nt2], ph[mt], vh0, vh1);
                    mma_bf16(o[mt][nt2], ph[mt], vl0, vl1);
                    mma_bf16(o[mt][nt2], pl[mt], vh0, vh1);
                }
            }
        }
    }

    // finalize
    #pragma unroll
    for (int q = 0; q < 4; q++){
        l[q] += __shfl_xor_sync(0xffffffffu, l[q], 1);
        l[q] += __shfl_xor_sync(0xffffffffu, l[q], 2);
        l[q] = 1.0f / l[q];
    }
    #pragma unroll
    for (int mt = 0; mt < 2; mt++){
        int r1 = wid*32 + mt*16 + gid, r2 = r1 + 8;
        float* o1 = out + (pixbase + (size_t)(r1>>4)*128 + (r1&15))*192 + h*32;
        float* o2 = out + (pixbase + (size_t)(r2>>4)*128 + (r2&15))*192 + h*32;
        #pragma unroll
        for (int nt2 = 0; nt2 < 4; nt2++){
            int dc = nt2*8 + 2*tig;
            float2 v1 = { o[mt][nt2][0]*l[2*mt],   o[mt][nt2][1]*l[2*mt] };
            float2 v2 = { o[mt][nt2][2]*l[2*mt+1], o[mt][nt2][3]*l[2*mt+1] };
            *(float2*)(o1 + dc) = v1;
            *(float2*)(o2 + dc) = v2;
        }
    }
}

// ---------------------------------------------------------------------------
extern "C" void kernel_launch(void* const* d_in, const int* in_sizes, int n_in,
                              void* d_out, int out_size)
{
    const float* x      = (const float*)d_in[0];
    const float* p1_w   = (const float*)d_in[1];
    const float* p1_b   = (const float*)d_in[2];
    const float* pw_w   = (const float*)d_in[3];
    const float* pw_b   = (const float*)d_in[4];
    const float* dw_w   = (const float*)d_in[5];
    const float* dw_b   = (const float*)d_in[6];
    const float* dd_w   = (const float*)d_in[7];
    const float* dd_b   = (const float*)d_in[8];
    const float* p2_w   = (const float*)d_in[9];
    const float* p2_b   = (const float*)d_in[10];
    const float* ln_g   = (const float*)d_in[11];
    const float* ln_b   = (const float*)d_in[12];
    const float* qkv_w  = (const float*)d_in[13];
    const float* q_bias = (const float*)d_in[14];
    const float* v_bias = (const float*)d_in[15];
    const float* lsc    = (const float*)d_in[16];
    const float* cpb_w1 = (const float*)d_in[17];
    const float* cpb_b1 = (const float*)d_in[18];
    const float* cpb_w2 = (const float*)d_in[19];
    const float* proj_w = (const float*)d_in[20];
    const float* proj_b = (const float*)d_in[21];
    float* outp = (float*)d_out;

    float *gy, *ga, *gb, *gq, *gt, *gbias;
    cudaGetSymbolAddress((void**)&gy, g_y);
    cudaGetSymbolAddress((void**)&ga, g_a);
    cudaGetSymbolAddress((void**)&gb, g_b);
    cudaGetSymbolAddress((void**)&gq, g_qkv);
    cudaGetSymbolAddress((void**)&gt, g_tbl);
    cudaGetSymbolAddress((void**)&gbias, g_bias);

    const int ATTN_SMEM = (2*16*264 + 2*128*40 + 256) * 4;   // ~75.8 KB
    cudaFuncSetAttribute(k_attn, cudaFuncAttributeMaxDynamicSharedMemorySize, ATTN_SMEM);
    const int GEMM_SMEM_LOAD  = (64*20*2 + 16*260*2) * 4;
    const int GEMM_SMEM_STAGE = 64*260*4;
    cudaFuncSetAttribute(k_gemm<2>, cudaFuncAttributeMaxDynamicSharedMemorySize, GEMM_SMEM_STAGE);
    cudaFuncSetAttribute(k_gemm<3>, cudaFuncAttributeMaxDynamicSharedMemorySize, GEMM_SMEM_STAGE);

    dim3 gNCHW(HW/256, 3, BATCH);

    // CPB bias table + expansion (independent of main chain)
    k_cpb<<<961, 128>>>(cpb_w1, cpb_b1, cpb_w2, gt);
    k_bias<<<dim3(256, NH), 256>>>(gt, gbias);

    // VAB conv block
    k_gemm<0><<<gNCHW, 256, GEMM_SMEM_LOAD>>>(x,  p1_w, p1_b, nullptr, nullptr, nullptr, nullptr, gy);
    k_gemm<1><<<gNCHW, 256, GEMM_SMEM_LOAD>>>(gy, pw_w, pw_b, nullptr, nullptr, nullptr, nullptr, ga);
    k_dwf<<<dim3(16, BATCH*C), 256>>>(ga, dw_w, dw_b, dd_w, dd_b, gb);
    k_gemm<2><<<gNCHW, 256, GEMM_SMEM_STAGE>>>(gy, p2_w, p2_b, gb, x, nullptr, nullptr, ga);

    // LayerNorm (BHWC)
    k_ln<<<NPIX/8, 256>>>(ga, ln_g, ln_b, gy);

    // QKV projection
    k_gemm<3><<<dim3(NPIX/256, 9), 256, GEMM_SMEM_STAGE>>>(gy, qkv_w, nullptr, nullptr, nullptr, q_bias, v_bias, gq);

    // Tensor-core windowed attention -> BHWC in ga
    k_attn<<<dim3(NWIN, NH), 256, ATTN_SMEM>>>(gq, gbias, lsc, ga);

    // Output projection -> NCHW d_out
    k_gemm<4><<<dim3(NPIX/256, 3), 256, GEMM_SMEM_LOAD>>>(ga, proj_w, proj_b, nullptr, nullptr, nullptr, nullptr, outp);
}